// round 14
// baseline (speedup 1.0000x reference)
#include <cuda_runtime.h>
#include <cuda_fp16.h>
#include <cstdint>

#define H_    56
#define W_    56
#define NH_   12
#define HD    64
#define NTOK  3137          // 56*56 + 1
#define C_    768
#define C3    2304
#define B_    8
#define MTOT  (B_ * NTOK)   // 25096
#define KDIM  768
#define BK    32
#define NSTG  (KDIM / BK)   // 24
#define NCH   8
#define KC    393           // ceil(NTOK / NCH)

typedef unsigned long long u64;

// ---------------- scratch (__device__ globals; no cudaMalloc allowed) -------
__device__ __half g_qkv[(size_t)MTOT * C3];   // fp16 QKV activations
__device__ float  g_att[(size_t)MTOT * C_];   // fp32 row-partial
__device__ float  g_sc [(size_t)B_ * NH_ * H_ * W_ * 64]; // col scores/probs
__device__ float  g_clsp[(size_t)B_ * NH_ * NCH * 66];    // cls partials
__device__ __half g_xh [(size_t)MTOT * C_];   // x in fp16
__device__ __half g_ath[(size_t)MTOT * C_];   // attention out fp16
__device__ __half g_wqh[(size_t)C3 * C_];     // W_qkv^T split  [N,K]
__device__ __half g_wql[(size_t)C3 * C_];
__device__ __half g_wph[(size_t)C_ * C_];     // W_proj^T split [N,K]
__device__ __half g_wpl[(size_t)C_ * C_];

__device__ __forceinline__ void hsplit2(float v, __half& h, __half& l) {
    h = __float2half(v);
    l = __float2half(v - __half2float(h));
}
__device__ __forceinline__ uint32_t hpack2(__half a, __half b) {
    return (uint32_t)__half_as_ushort(a) |
           ((uint32_t)__half_as_ushort(b) << 16);
}
__device__ __forceinline__ uint32_t su32(const void* p) {
    uint32_t a;
    asm("{ .reg .u64 t; cvta.to.shared.u64 t, %1; cvt.u32.u64 %0, t; }"
        : "=r"(a) : "l"(p));
    return a;
}
__device__ __forceinline__ void cp16(uint32_t dst, const void* src, bool ok) {
    int sz = ok ? 16 : 0;
    asm volatile("cp.async.cg.shared.global [%0], [%1], 16, %2;"
                 :: "r"(dst), "l"(src), "r"(sz) : "memory");
}
__device__ __forceinline__ void mma16816(float* c, const uint32_t* a, const uint32_t* b) {
    asm volatile(
        "mma.sync.aligned.m16n8k16.row.col.f32.f16.f16.f32 "
        "{%0,%1,%2,%3}, {%4,%5,%6,%7}, {%8,%9}, {%0,%1,%2,%3};"
        : "+f"(c[0]), "+f"(c[1]), "+f"(c[2]), "+f"(c[3])
        : "r"(a[0]), "r"(a[1]), "r"(a[2]), "r"(a[3]), "r"(b[0]), "r"(b[1]));
}
__device__ __forceinline__ void ldsm4(uint32_t& r0, uint32_t& r1, uint32_t& r2,
                                      uint32_t& r3, uint32_t addr) {
    asm volatile("ldmatrix.sync.aligned.m8n8.x4.shared.b16 {%0,%1,%2,%3}, [%4];"
                 : "=r"(r0), "=r"(r1), "=r"(r2), "=r"(r3) : "r"(addr));
}
__device__ __forceinline__ void ldsm4t(uint32_t& r0, uint32_t& r1, uint32_t& r2,
                                       uint32_t& r3, uint32_t addr) {
    asm volatile("ldmatrix.sync.aligned.m8n8.x4.trans.shared.b16 {%0,%1,%2,%3}, [%4];"
                 : "=r"(r0), "=r"(r1), "=r"(r2), "=r"(r3) : "r"(addr));
}

// ---------------- pre-pass: fp32 -> fp16 ------------------------------------
__global__ __launch_bounds__(256) void k_split(
    const float* __restrict__ in, __half* __restrict__ hi, int n4)
{
    int i = blockIdx.x * 256 + threadIdx.x;
    if (i >= n4) return;
    float4 v = ((const float4*)in)[i];
    __half hv[4];
    hv[0] = __float2half(v.x);
    hv[1] = __float2half(v.y);
    hv[2] = __float2half(v.z);
    hv[3] = __float2half(v.w);
    ((uint2*)hi)[i] = *(uint2*)hv;
}

// ---------------- pre-pass: transpose + fp16 split weights ------------------
__global__ __launch_bounds__(256) void k_tsplit(
    const float* __restrict__ W, __half* __restrict__ th,
    __half* __restrict__ tl, int R, int Cn)
{
    __shared__ float t[32][33];
    int x = blockIdx.x * 32 + threadIdx.x;
    int y = blockIdx.y * 32 + threadIdx.y;
#pragma unroll
    for (int j = 0; j < 32; j += 8)
        t[threadIdx.y + j][threadIdx.x] = W[(size_t)(y + j) * Cn + x];
    __syncthreads();
    int ox = blockIdx.y * 32 + threadIdx.x;
    int oy = blockIdx.x * 32 + threadIdx.y;
#pragma unroll
    for (int j = 0; j < 32; j += 8) {
        float v = t[threadIdx.x][threadIdx.y + j];
        __half h, l;
        hsplit2(v, h, l);
        th[(size_t)(oy + j) * R + ox] = h;
        tl[(size_t)(oy + j) * R + ox] = l;
    }
}

// ---------------- fp16x2 GEMM: C = Ah[M,K] @ (Bh+Bl)[N,K]^T -----------------
// fp32 out (+bias) when Oh==null, else fp16 out.
#define TS2     8192
#define STG2    (3 * TS2)
#define GEMM_SMEM (3 * STG2)

__global__ __launch_bounds__(256) void gemm_mma(
    const __half* __restrict__ Ah,
    const __half* __restrict__ Bh, const __half* __restrict__ Bl,
    float* __restrict__ Cc, const float* __restrict__ bias,
    __half* __restrict__ Oh, int M, int N)
{
    extern __shared__ __align__(128) char smem[];
    const uint32_t sb = su32(smem);
    const int tid  = threadIdx.x;
    const int wid  = tid >> 5, lane = tid & 31;
    const int gid  = lane >> 2, tig = lane & 3;
    const int wm   = wid & 1, wn = wid >> 1;
    const int row0 = blockIdx.y * 128, col0 = blockIdx.x * 128;

    float acc[4][4][4];
#pragma unroll
    for (int i = 0; i < 4; ++i)
#pragma unroll
        for (int j = 0; j < 4; ++j)
#pragma unroll
            for (int k = 0; k < 4; ++k) acc[i][j][k] = 0.f;

    const int rlA = (lane & 7) + ((lane >> 3) & 1) * 8;
    const int kcA = (lane >> 4) & 1;
    const int swA = (rlA >> 1) & 3;
    const int rlB = (lane & 7) + ((lane >> 4) & 1) * 8;
    const int kcB = (lane >> 3) & 1;
    const int swB = (rlB >> 1) & 3;
    const uint32_t aRow = (uint32_t)(wm * 64 + rlA) * 64u;
    const uint32_t bRow = (uint32_t)(wn * 32 + rlB) * 64u;

    const int r0c = tid >> 2, j0c = tid & 3;
    const int r1c = (tid + 256) >> 2, j1c = tid & 3;

    auto issue = [&](int c) {
        const int k0 = c * BK;
        const uint32_t stg = sb + (uint32_t)(c % 3) * STG2;
#pragma unroll
        for (int rep = 0; rep < 2; ++rep) {
            const int row = rep ? r1c : r0c;
            const int j   = rep ? j1c : j0c;
            const uint32_t d = stg + (uint32_t)row * 64u
                             + (uint32_t)((j ^ ((row >> 1) & 3)) * 16);
            const int grA = row0 + row;
            const bool okA = grA < M;
            const size_t aoff = (size_t)(okA ? grA : 0) * KDIM + k0 + j * 8;
            cp16(d, Ah + aoff, okA);
            const size_t boff = (size_t)(col0 + row) * KDIM + k0 + j * 8;
            cp16(d + TS2,     Bh + boff, true);
            cp16(d + 2 * TS2, Bl + boff, true);
        }
        asm volatile("cp.async.commit_group;" ::: "memory");
    };

    issue(0);
    issue(1);

    for (int c = 0; c < NSTG; ++c) {
        asm volatile("cp.async.wait_group 1;" ::: "memory");
        __syncthreads();
        if (c + 2 < NSTG) issue(c + 2);

        const uint32_t stg = sb + (uint32_t)(c % 3) * STG2;

#pragma unroll
        for (int kk = 0; kk < 2; ++kk) {
            const uint32_t aCh = (uint32_t)(((kcA + 2 * kk) ^ swA) * 16);
            const uint32_t bCh = (uint32_t)(((kcB + 2 * kk) ^ swB) * 16);
            uint32_t ah[4][4], bh[4][2], bl[4][2];
#pragma unroll
            for (int mt = 0; mt < 4; ++mt) {
                const uint32_t aAd = stg + aRow + mt * (16 * 64) + aCh;
                ldsm4(ah[mt][0], ah[mt][1], ah[mt][2], ah[mt][3], aAd);
            }
#pragma unroll
            for (int pr = 0; pr < 2; ++pr) {
                const uint32_t bAd = stg + bRow + pr * (16 * 64) + bCh;
                ldsm4(bh[2 * pr][0], bh[2 * pr][1], bh[2 * pr + 1][0], bh[2 * pr + 1][1],
                      bAd + TS2);
                ldsm4(bl[2 * pr][0], bl[2 * pr][1], bl[2 * pr + 1][0], bl[2 * pr + 1][1],
                      bAd + 2 * TS2);
            }
#pragma unroll
            for (int mt = 0; mt < 4; ++mt)
#pragma unroll
                for (int nt = 0; nt < 4; ++nt) mma16816(acc[mt][nt], ah[mt], bh[nt]);
#pragma unroll
            for (int mt = 0; mt < 4; ++mt)
#pragma unroll
                for (int nt = 0; nt < 4; ++nt) mma16816(acc[mt][nt], ah[mt], bl[nt]);
        }
    }

#pragma unroll
    for (int mt = 0; mt < 4; ++mt) {
        const int gr = row0 + wm * 64 + mt * 16 + gid;
#pragma unroll
        for (int nt = 0; nt < 4; ++nt) {
            const int gc = col0 + wn * 32 + nt * 8 + tig * 2;
            if (Oh != nullptr) {
                if (gr < M)
                    *(uint32_t*)(Oh + (size_t)gr * N + gc) =
                        hpack2(__float2half(acc[mt][nt][0]), __float2half(acc[mt][nt][1]));
                if (gr + 8 < M)
                    *(uint32_t*)(Oh + (size_t)(gr + 8) * N + gc) =
                        hpack2(__float2half(acc[mt][nt][2]), __float2half(acc[mt][nt][3]));
            } else {
                float b0 = 0.f, b1 = 0.f;
                if (bias) { b0 = __ldg(bias + gc); b1 = __ldg(bias + gc + 1); }
                if (gr < M)
                    *(float2*)(Cc + (size_t)gr * N + gc) =
                        make_float2(acc[mt][nt][0] + b0, acc[mt][nt][1] + b1);
                if (gr + 8 < M)
                    *(float2*)(Cc + (size_t)(gr + 8) * N + gc) =
                        make_float2(acc[mt][nt][2] + b0, acc[mt][nt][3] + b1);
            }
        }
    }
}

// ============================================================================
// Attention MMA helpers: 64x64 fp16 tiles, 128B rows, chunk swizzle c^(row&7)
// ============================================================================
#define ATS 8192   // one 64x64 fp16 tile

// 1-pass fp16 MMA over a 64x64x64 tile pair. acc[8][4] per warp (16 m-rows).
// TRANS=false: B rows = n (keys), k along row. TRANS=true: B rows = k, n along row.
template <bool TRANS>
__device__ __forceinline__ void att_mma64(
    float (&acc)[8][4], uint32_t sA, uint32_t sB, int m0, int lane)
{
    const int rA = (lane & 7) + ((lane >> 3) & 1) * 8;
    const int cA = (lane >> 4) & 1;
#pragma unroll
    for (int s = 0; s < 4; ++s) {
        uint32_t a[4];
        {
            const int row = m0 + rA;
            const uint32_t ad = sA + (uint32_t)row * 128u
                              + (uint32_t)(((2 * s + cA) ^ (row & 7)) * 16);
            ldsm4(a[0], a[1], a[2], a[3], ad);
        }
        uint32_t bb[8][2];
#pragma unroll
        for (int p = 0; p < 4; ++p) {
            uint32_t ad;
            if (TRANS) {
                const int row = s * 16 + (lane & 7) + ((lane >> 3) & 1) * 8;
                const int ch  = 2 * p + ((lane >> 4) & 1);
                ad = sB + (uint32_t)row * 128u + (uint32_t)((ch ^ (row & 7)) * 16);
                ldsm4t(bb[2 * p][0], bb[2 * p][1], bb[2 * p + 1][0], bb[2 * p + 1][1], ad);
            } else {
                const int row = p * 16 + (lane & 7) + ((lane >> 4) & 1) * 8;
                const int ch  = 2 * s + ((lane >> 3) & 1);
                ad = sB + (uint32_t)row * 128u + (uint32_t)((ch ^ (row & 7)) * 16);
                ldsm4(bb[2 * p][0], bb[2 * p][1], bb[2 * p + 1][0], bb[2 * p + 1][1], ad);
            }
        }
#pragma unroll
        for (int nt = 0; nt < 8; ++nt) mma16816(acc[nt], a, bb[nt]);
    }
}

// load one 64-row fp16 tile from qkv (row length 64 halves = 128B, swizzled)
#define TILE_LOAD1(T, NMAP, RMAX, GOFF)                                        \
    for (int idx = tid; idx < 512; idx += 128) {                               \
        const int r = idx >> 3, cc = idx & 7;                                  \
        const uint32_t d = (uint32_t)r * 128u + (uint32_t)((cc ^ (r & 7)) * 16); \
        uint4 v = make_uint4(0, 0, 0, 0);                                      \
        if (r < (RMAX)) {                                                      \
            const int n = (NMAP);                                              \
            v = *(const uint4*)(qk + (size_t)n * C3 + (GOFF) + cc * 8);        \
        }                                                                      \
        *(uint4*)((T) + d) = v;                                                \
    }

// ============================================================================
// Phase 1: column scores via fp16 MMA. Block=(w, head, b), 128 threads.
// ============================================================================
__global__ __launch_bounds__(128) void k_colscore(
    const __half* __restrict__ qkv, float* __restrict__ sc)
{
    __shared__ __align__(16) char sm[2 * ATS];
    char* T0 = sm;              // Q
    char* T2 = sm + ATS;        // K
    const int w = blockIdx.x, head = blockIdx.y, b = blockIdx.z;
    const int tid = threadIdx.x, wid = tid >> 5, lane = tid & 31;
    const __half* qk = qkv + (size_t)b * NTOK * C3;
    const int qoff = head * HD;

    TILE_LOAD1(T0, 1 + r * W_ + w, 56, qoff)
    TILE_LOAD1(T2, (r == 0) ? 0 : (1 + (r - 1) * W_ + w), 57, C_ + qoff)
    __syncthreads();

    float acc[8][4];
#pragma unroll
    for (int i = 0; i < 8; ++i)
#pragma unroll
        for (int j = 0; j < 4; ++j) acc[i][j] = 0.f;

    att_mma64<false>(acc, su32(T0), su32(T2), wid * 16, lane);

    float* out = sc + ((((size_t)b * NH_ + head) * H_) * W_ + w) * 64;
    const int crow = wid * 16 + (lane >> 2);
    const int ccol = (lane & 3) * 2;
#pragma unroll
    for (int nt = 0; nt < 8; ++nt)
#pragma unroll
        for (int i = 0; i < 4; ++i) {
            const int row = crow + (i >> 1) * 8;
            const int col = nt * 8 + ccol + (i & 1);
            if (row < 56 && col < 57)
                out[(size_t)row * (W_ * 64) + col] = acc[nt][i] * 0.125f;
        }
}

// ============================================================================
// Phase 2: row scores (MMA) + full softmax + row P·V (MMA).
// Block=(h, head, b), 128 threads, dynamic smem.
// ============================================================================
#define PST 132
#define RF_SMEM (2 * ATS + 64 * PST * 4)   // 16384 + 33792 = 50176

__global__ __launch_bounds__(128) void k_rowfused(
    const __half* __restrict__ qkv, float* __restrict__ sc,
    float* __restrict__ attp)
{
    extern __shared__ __align__(16) char dsm[];
    char* T0 = dsm;              // Q -> P(fp16)
    char* T2 = dsm + ATS;        // K -> V
    float* P = (float*)(dsm + 2 * ATS);

    const int h = blockIdx.x, head = blockIdx.y, b = blockIdx.z;
    const int tid = threadIdx.x, wid = tid >> 5, lane = tid & 31;
    const __half* qk = qkv + (size_t)b * NTOK * C3;
    const int qoff = head * HD;
    const int nrow0 = 1 + h * W_;

    TILE_LOAD1(T0, nrow0 + r, 56, qoff)
    TILE_LOAD1(T2, nrow0 + r, 56, C_ + qoff)
    __syncthreads();

    // row scores
    {
        float acc[8][4];
#pragma unroll
        for (int i = 0; i < 8; ++i)
#pragma unroll
            for (int j = 0; j < 4; ++j) acc[i][j] = 0.f;
        att_mma64<false>(acc, su32(T0), su32(T2), wid * 16, lane);

        const int crow = wid * 16 + (lane >> 2);
        const int ccol = (lane & 3) * 2;
#pragma unroll
        for (int nt = 0; nt < 8; ++nt)
#pragma unroll
            for (int i = 0; i < 4; ++i) {
                const int row = crow + (i >> 1) * 8;
                const int col = nt * 8 + ccol + (i & 1);
                float v = acc[nt][i] * 0.125f;
                if (col == row || col >= 56) v = -1e30f;
                P[row * PST + 60 + col] = v;
            }
    }
    __syncthreads();

    // load col scores into P[:, 0..56]; reload V into T2
    {
        const float* scb = sc + ((((size_t)b * NH_ + head) * H_ + h) * W_) * 64;
        for (int idx = tid; idx < 56 * 57; idx += 128) {
            const int q = idx / 57, j = idx % 57;
            P[q * PST + j] = scb[(size_t)q * 64 + j];
        }
    }
    TILE_LOAD1(T2, nrow0 + r, 56, 2 * C_ + qoff)
    __syncthreads();

    // softmax over 113 (cols 0..56 and 60..115)
    if (tid < 56) {
        float* row = P + tid * PST;
        float m = -1e30f;
#pragma unroll 4
        for (int j = 0; j < 57; ++j) m = fmaxf(m, row[j]);
#pragma unroll 4
        for (int j = 60; j < 116; ++j) m = fmaxf(m, row[j]);
        float s = 0.f;
#pragma unroll 4
        for (int j = 0; j < 57; ++j) { float e = __expf(row[j] - m); row[j] = e; s += e; }
#pragma unroll 4
        for (int j = 60; j < 116; ++j) { float e = __expf(row[j] - m); row[j] = e; s += e; }
        const float inv = 1.f / s;
#pragma unroll 4
        for (int j = 0; j < 57; ++j) row[j] *= inv;
#pragma unroll 4
        for (int j = 60; j < 116; ++j) row[j] *= inv;
    }
    __syncthreads();

    // write col probs back; convert row probs to fp16 tile in T0
    {
        float* scb = sc + ((((size_t)b * NH_ + head) * H_ + h) * W_) * 64;
        for (int idx = tid; idx < 56 * 57; idx += 128) {
            const int q = idx / 57, j = idx % 57;
            scb[(size_t)q * 64 + j] = P[q * PST + j];
        }
        for (int idx = tid; idx < 4096; idx += 128) {
            const int q = idx >> 6, k = idx & 63;
            float v = (q < 56 && k < 56) ? P[q * PST + 60 + k] : 0.f;
            const uint32_t d = (uint32_t)q * 128u
                             + (uint32_t)((((k >> 3) ^ (q & 7)) * 16) + (k & 7) * 2);
            *(__half*)(T0 + d) = __float2half(v);
        }
    }
    __syncthreads();

    // row aggregation: P[64(q) x 64(k)] @ V[64(k) x 64(d)] (V trans-loaded)
    {
        float acc[8][4];
#pragma unroll
        for (int i = 0; i < 8; ++i)
#pragma unroll
            for (int j = 0; j < 4; ++j) acc[i][j] = 0.f;
        att_mma64<true>(acc, su32(T0), su32(T2), wid * 16, lane);

        const int crow = wid * 16 + (lane >> 2);
        const int ccol = (lane & 3) * 2;
#pragma unroll
        for (int nt = 0; nt < 8; ++nt) {
            const int col = nt * 8 + ccol;
            const int r0 = crow, r1 = crow + 8;
            if (r0 < 56)
                *(float2*)(attp + ((size_t)b * NTOK + nrow0 + r0) * C_ + qoff + col)
                    = make_float2(acc[nt][0], acc[nt][1]);
            if (r1 < 56)
                *(float2*)(attp + ((size_t)b * NTOK + nrow0 + r1) * C_ + qoff + col)
                    = make_float2(acc[nt][2], acc[nt][3]);
        }
    }
}

// ============================================================================
// Phase 3: column aggregation (MMA) + fp16 emit. Block=(w, head, b).
// ============================================================================
__global__ __launch_bounds__(128) void k_colagg(
    const __half* __restrict__ qkv, const float* __restrict__ sc,
    const float* __restrict__ attp, __half* __restrict__ outh)
{
    __shared__ __align__(16) char sm[2 * ATS];
    char* T0 = sm;              // P col (fp16)
    char* T2 = sm + ATS;        // V col
    const int w = blockIdx.x, head = blockIdx.y, b = blockIdx.z;
    const int tid = threadIdx.x, wid = tid >> 5, lane = tid & 31;
    const __half* qk = qkv + (size_t)b * NTOK * C3;
    const int qoff = head * HD;

    TILE_LOAD1(T2, (r == 0) ? 0 : (1 + (r - 1) * W_ + w), 57, 2 * C_ + qoff)
    {
        const float* scb = sc + (((size_t)b * NH_ + head) * H_) * (W_ * 64)
                         + (size_t)w * 64;
        for (int idx = tid; idx < 4096; idx += 128) {
            const int q = idx >> 6, k = idx & 63;
            float v = (q < 56 && k < 57) ? scb[(size_t)q * (W_ * 64) + k] : 0.f;
            const uint32_t d = (uint32_t)q * 128u
                             + (uint32_t)((((k >> 3) ^ (q & 7)) * 16) + (k & 7) * 2);
            *(__half*)(T0 + d) = __float2half(v);
        }
    }
    __syncthreads();

    float acc[8][4];
#pragma unroll
    for (int i = 0; i < 8; ++i)
#pragma unroll
        for (int j = 0; j < 4; ++j) acc[i][j] = 0.f;
    att_mma64<true>(acc, su32(T0), su32(T2), wid * 16, lane);

    const int crow = wid * 16 + (lane >> 2);
    const int ccol = (lane & 3) * 2;
#pragma unroll
    for (int nt = 0; nt < 8; ++nt) {
        const int col = nt * 8 + ccol;
#pragma unroll
        for (int half = 0; half < 2; ++half) {
            const int row = crow + half * 8;
            if (row >= 56) continue;
            const size_t off = ((size_t)b * NTOK + 1 + row * W_ + w) * C_ + qoff + col;
            const float2 rp = *(const float2*)(attp + off);
            *(uint32_t*)(outh + off) =
                hpack2(__float2half(acc[nt][2 * half + 0] + rp.x),
                       __float2half(acc[nt][2 * half + 1] + rp.y));
        }
    }
}

// ---------------- CLS-token attention: split-K partials + reduce ------------
__global__ __launch_bounds__(256) void cls_part(
    const __half* __restrict__ qkv, float* __restrict__ clsp)
{
    const int nh = blockIdx.x, b = blockIdx.y, ch = blockIdx.z;
    const int tid = threadIdx.x;
    const int n0 = ch * KC;
    const int n1 = min(NTOK, n0 + KC);
    const int cnt = n1 - n0;

    __shared__ float qs[HD];
    __shared__ float scs[KC];
    __shared__ float red[256];
    __shared__ float part[4][HD];

    const __half* base = qkv + (size_t)b * NTOK * C3;
    if (tid < HD) qs[tid] = __half2float(base[nh * HD + tid]);
    __syncthreads();

    for (int i = tid; i < cnt; i += 256) {
        const __half2* kp = (const __half2*)(base + (size_t)(n0 + i) * C3 + C_ + nh * HD);
        float s = 0.f;
#pragma unroll
        for (int d = 0; d < HD / 2; ++d) {
            float2 kv = __half22float2(kp[d]);
            s += qs[2 * d] * kv.x + qs[2 * d + 1] * kv.y;
        }
        scs[i] = s * 0.125f;
    }
    __syncthreads();

    float m = -1e30f;
    for (int i = tid; i < cnt; i += 256) m = fmaxf(m, scs[i]);
    red[tid] = m;
    __syncthreads();
    for (int st = 128; st; st >>= 1) {
        if (tid < st) red[tid] = fmaxf(red[tid], red[tid + st]);
        __syncthreads();
    }
    m = red[0];
    __syncthreads();

    float s = 0.f;
    for (int i = tid; i < cnt; i += 256) {
        float e = __expf(scs[i] - m);
        scs[i] = e;
        s += e;
    }
    red[tid] = s;
    __syncthreads();
    for (int st = 128; st; st >>= 1) {
        if (tid < st) red[tid] += red[tid + st];
        __syncthreads();
    }
    const float S = red[0];
    __syncthreads();

    const int d = tid & 63, kq = tid >> 6;
    float acc = 0.f;
    for (int i = kq; i < cnt; i += 4)
        acc += scs[i] * __half2float(base[(size_t)(n0 + i) * C3 + 2 * C_ + nh * HD + d]);
    part[kq][d] = acc;
    __syncthreads();
    if (kq == 0) {
        float* o = clsp + ((size_t)(b * NH_ + nh) * NCH + ch) * 66;
        o[d] = part[0][d] + part[1][d] + part[2][d] + part[3][d];
        if (d == 0) { o[64] = m; o[65] = S; }
    }
}

__global__ __launch_bounds__(64) void cls_reduce(
    const float* __restrict__ clsp, __half* __restrict__ outh)
{
    const int nh = blockIdx.x, b = blockIdx.y;
    const int d = threadIdx.x;
    const float* o = clsp + (size_t)(b * NH_ + nh) * NCH * 66;
    float M = -1e30f;
#pragma unroll
    for (int c = 0; c < NCH; ++c) M = fmaxf(M, o[c * 66 + 64]);
    float S = 0.f, A = 0.f;
#pragma unroll
    for (int c = 0; c < NCH; ++c) {
        const float wgt = __expf(o[c * 66 + 64] - M);
        S += o[c * 66 + 65] * wgt;
        A += o[c * 66 + d] * wgt;
    }
    outh[(size_t)b * NTOK * C_ + nh * HD + d] = __float2half(A / S);
}

// ---------------------------------------------------------------------------
extern "C" void kernel_launch(void* const* d_in, const int* in_sizes, int n_in,
                              void* d_out, int out_size)
{
    const float* x     = (const float*)d_in[0];
    const float* Wqkv  = (const float*)d_in[1];
    const float* Wproj = (const float*)d_in[2];
    const float* bproj = (const float*)d_in[3];
    float* out = (float*)d_out;

    float *att, *sc, *clsp;
    __half *qkv, *xh, *ath, *wqh, *wql, *wph, *wpl;
    cudaGetSymbolAddress((void**)&qkv,  g_qkv);
    cudaGetSymbolAddress((void**)&att,  g_att);
    cudaGetSymbolAddress((void**)&sc,   g_sc);
    cudaGetSymbolAddress((void**)&clsp, g_clsp);
    cudaGetSymbolAddress((void**)&xh,   g_xh);
    cudaGetSymbolAddress((void**)&ath,  g_ath);
    cudaGetSymbolAddress((void**)&wqh,  g_wqh);
    cudaGetSymbolAddress((void**)&wql,  g_wql);
    cudaGetSymbolAddress((void**)&wph,  g_wph);
    cudaGetSymbolAddress((void**)&wpl,  g_wpl);

    cudaFuncSetAttribute(gemm_mma,
                         cudaFuncAttributeMaxDynamicSharedMemorySize, GEMM_SMEM);
    cudaFuncSetAttribute(k_rowfused,
                         cudaFuncAttributeMaxDynamicSharedMemorySize, RF_SMEM);

    // 0) pre-passes
    {
        int n4 = MTOT * C_ / 4;
        k_split<<<(n4 + 255) / 256, 256>>>(x, xh, n4);
        k_tsplit<<<dim3(C3 / 32, C_ / 32), dim3(32, 8)>>>(Wqkv,  wqh, wql, C_, C3);
        k_tsplit<<<dim3(C_ / 32, C_ / 32), dim3(32, 8)>>>(Wproj, wph, wpl, C_, C_);
    }
    // 1) QKV projection -> fp16 qkv
    gemm_mma<<<dim3(C3 / 128, (MTOT + 127) / 128), 256, GEMM_SMEM>>>(
        xh, wqh, wql, nullptr, nullptr, qkv, MTOT, C3);
    // 2) attention phases (fp16 MMA)
    {
        dim3 ag(W_, NH_, B_);
        k_colscore<<<ag, 128>>>(qkv, sc);
        dim3 rg(H_, NH_, B_);
        k_rowfused<<<rg, 128, RF_SMEM>>>(qkv, sc, att);
        cls_part<<<dim3(NH_, B_, NCH), 256>>>(qkv, clsp);
        cls_reduce<<<dim3(NH_, B_), 64>>>(clsp, ath);
        k_colagg<<<ag, 128>>>(qkv, sc, att, ath);
    }
    // 3) output projection + bias (fp32 out)
    gemm_mma<<<dim3(C_ / 128, (MTOT + 127) / 128), 256, GEMM_SMEM>>>(
        ath, wph, wpl, out, bproj, nullptr, MTOT, C_);
}

// round 15
// speedup vs baseline: 1.4764x; 1.4764x over previous
#include <cuda_runtime.h>
#include <cuda_fp16.h>
#include <cstdint>

#define H_    56
#define W_    56
#define NH_   12
#define HD    64
#define NTOK  3137          // 56*56 + 1
#define C_    768
#define C3    2304
#define B_    8
#define MTOT  (B_ * NTOK)   // 25096
#define KDIM  768
#define BK    32
#define NSTG  (KDIM / BK)   // 24
#define NCH   8
#define KC    393           // ceil(NTOK / NCH)

typedef unsigned long long u64;

// ---------------- scratch (__device__ globals; no cudaMalloc allowed) -------
__device__ __half g_qkv[(size_t)MTOT * C3];   // fp16 QKV activations
__device__ float  g_att[(size_t)MTOT * C_];   // fp32 row-partial
__device__ float  g_sc [(size_t)B_ * NH_ * H_ * W_ * 64]; // col scores/probs
__device__ float  g_clsp[(size_t)B_ * NH_ * NCH * 66];    // cls partials
__device__ __half g_xh [(size_t)MTOT * C_];   // x in fp16
__device__ __half g_ath[(size_t)MTOT * C_];   // attention out fp16
__device__ __half g_wqh[(size_t)C3 * C_];     // W_qkv^T split  [N,K]
__device__ __half g_wql[(size_t)C3 * C_];
__device__ __half g_wph[(size_t)C_ * C_];     // W_proj^T split [N,K]
__device__ __half g_wpl[(size_t)C_ * C_];

__device__ __forceinline__ void hsplit2(float v, __half& h, __half& l) {
    h = __float2half(v);
    l = __float2half(v - __half2float(h));
}
__device__ __forceinline__ uint32_t hpack2(__half a, __half b) {
    return (uint32_t)__half_as_ushort(a) |
           ((uint32_t)__half_as_ushort(b) << 16);
}
__device__ __forceinline__ uint32_t su32(const void* p) {
    uint32_t a;
    asm("{ .reg .u64 t; cvta.to.shared.u64 t, %1; cvt.u32.u64 %0, t; }"
        : "=r"(a) : "l"(p));
    return a;
}
__device__ __forceinline__ void cp16(uint32_t dst, const void* src, bool ok) {
    int sz = ok ? 16 : 0;
    asm volatile("cp.async.cg.shared.global [%0], [%1], 16, %2;"
                 :: "r"(dst), "l"(src), "r"(sz) : "memory");
}
__device__ __forceinline__ void mma16816(float* c, const uint32_t* a, const uint32_t* b) {
    asm volatile(
        "mma.sync.aligned.m16n8k16.row.col.f32.f16.f16.f32 "
        "{%0,%1,%2,%3}, {%4,%5,%6,%7}, {%8,%9}, {%0,%1,%2,%3};"
        : "+f"(c[0]), "+f"(c[1]), "+f"(c[2]), "+f"(c[3])
        : "r"(a[0]), "r"(a[1]), "r"(a[2]), "r"(a[3]), "r"(b[0]), "r"(b[1]));
}
__device__ __forceinline__ void ldsm4(uint32_t& r0, uint32_t& r1, uint32_t& r2,
                                      uint32_t& r3, uint32_t addr) {
    asm volatile("ldmatrix.sync.aligned.m8n8.x4.shared.b16 {%0,%1,%2,%3}, [%4];"
                 : "=r"(r0), "=r"(r1), "=r"(r2), "=r"(r3) : "r"(addr));
}
__device__ __forceinline__ void ldsm4t(uint32_t& r0, uint32_t& r1, uint32_t& r2,
                                       uint32_t& r3, uint32_t addr) {
    asm volatile("ldmatrix.sync.aligned.m8n8.x4.trans.shared.b16 {%0,%1,%2,%3}, [%4];"
                 : "=r"(r0), "=r"(r1), "=r"(r2), "=r"(r3) : "r"(addr));
}

// ---------------- pre-pass: fp32 -> fp16 ------------------------------------
__global__ __launch_bounds__(256) void k_split(
    const float* __restrict__ in, __half* __restrict__ hi, int n4)
{
    int i = blockIdx.x * 256 + threadIdx.x;
    if (i >= n4) return;
    float4 v = ((const float4*)in)[i];
    __half hv[4];
    hv[0] = __float2half(v.x);
    hv[1] = __float2half(v.y);
    hv[2] = __float2half(v.z);
    hv[3] = __float2half(v.w);
    ((uint2*)hi)[i] = *(uint2*)hv;
}

// ---------------- pre-pass: transpose + fp16 split weights ------------------
__global__ __launch_bounds__(256) void k_tsplit(
    const float* __restrict__ W, __half* __restrict__ th,
    __half* __restrict__ tl, int R, int Cn)
{
    __shared__ float t[32][33];
    int x = blockIdx.x * 32 + threadIdx.x;
    int y = blockIdx.y * 32 + threadIdx.y;
#pragma unroll
    for (int j = 0; j < 32; j += 8)
        t[threadIdx.y + j][threadIdx.x] = W[(size_t)(y + j) * Cn + x];
    __syncthreads();
    int ox = blockIdx.y * 32 + threadIdx.x;
    int oy = blockIdx.x * 32 + threadIdx.y;
#pragma unroll
    for (int j = 0; j < 32; j += 8) {
        float v = t[threadIdx.x][threadIdx.y + j];
        __half h, l;
        hsplit2(v, h, l);
        th[(size_t)(oy + j) * R + ox] = h;
        tl[(size_t)(oy + j) * R + ox] = l;
    }
}

// ---------------- fp16x2 GEMM: C = Ah[M,K] @ (Bh+Bl)[N,K]^T -----------------
// fp32 out (+bias) when Oh==null, else fp16 out staged via smem (coalesced).
#define TS2     8192
#define STG2    (3 * TS2)
#define GEMM_SMEM (3 * STG2)          // 73728 B (also covers 128x136 fp16 C tile)
#define CST     136                   // C-tile smem row stride in halves

__global__ __launch_bounds__(256) void gemm_mma(
    const __half* __restrict__ Ah,
    const __half* __restrict__ Bh, const __half* __restrict__ Bl,
    float* __restrict__ Cc, const float* __restrict__ bias,
    __half* __restrict__ Oh, int M, int N)
{
    extern __shared__ __align__(128) char smem[];
    const uint32_t sb = su32(smem);
    const int tid  = threadIdx.x;
    const int wid  = tid >> 5, lane = tid & 31;
    const int gid  = lane >> 2, tig = lane & 3;
    const int wm   = wid & 1, wn = wid >> 1;
    const int row0 = blockIdx.y * 128, col0 = blockIdx.x * 128;

    float acc[4][4][4];
#pragma unroll
    for (int i = 0; i < 4; ++i)
#pragma unroll
        for (int j = 0; j < 4; ++j)
#pragma unroll
            for (int k = 0; k < 4; ++k) acc[i][j][k] = 0.f;

    const int rlA = (lane & 7) + ((lane >> 3) & 1) * 8;
    const int kcA = (lane >> 4) & 1;
    const int swA = (rlA >> 1) & 3;
    const int rlB = (lane & 7) + ((lane >> 4) & 1) * 8;
    const int kcB = (lane >> 3) & 1;
    const int swB = (rlB >> 1) & 3;
    const uint32_t aRow = (uint32_t)(wm * 64 + rlA) * 64u;
    const uint32_t bRow = (uint32_t)(wn * 32 + rlB) * 64u;

    const int r0c = tid >> 2, j0c = tid & 3;
    const int r1c = (tid + 256) >> 2, j1c = tid & 3;

    auto issue = [&](int c) {
        const int k0 = c * BK;
        const uint32_t stg = sb + (uint32_t)(c % 3) * STG2;
#pragma unroll
        for (int rep = 0; rep < 2; ++rep) {
            const int row = rep ? r1c : r0c;
            const int j   = rep ? j1c : j0c;
            const uint32_t d = stg + (uint32_t)row * 64u
                             + (uint32_t)((j ^ ((row >> 1) & 3)) * 16);
            const int grA = row0 + row;
            const bool okA = grA < M;
            const size_t aoff = (size_t)(okA ? grA : 0) * KDIM + k0 + j * 8;
            cp16(d, Ah + aoff, okA);
            const size_t boff = (size_t)(col0 + row) * KDIM + k0 + j * 8;
            cp16(d + TS2,     Bh + boff, true);
            cp16(d + 2 * TS2, Bl + boff, true);
        }
        asm volatile("cp.async.commit_group;" ::: "memory");
    };

    issue(0);
    issue(1);

    for (int c = 0; c < NSTG; ++c) {
        asm volatile("cp.async.wait_group 1;" ::: "memory");
        __syncthreads();
        if (c + 2 < NSTG) issue(c + 2);

        const uint32_t stg = sb + (uint32_t)(c % 3) * STG2;

#pragma unroll
        for (int kk = 0; kk < 2; ++kk) {
            const uint32_t aCh = (uint32_t)(((kcA + 2 * kk) ^ swA) * 16);
            const uint32_t bCh = (uint32_t)(((kcB + 2 * kk) ^ swB) * 16);
            uint32_t ah[4][4], bh[4][2], bl[4][2];
#pragma unroll
            for (int mt = 0; mt < 4; ++mt) {
                const uint32_t aAd = stg + aRow + mt * (16 * 64) + aCh;
                ldsm4(ah[mt][0], ah[mt][1], ah[mt][2], ah[mt][3], aAd);
            }
#pragma unroll
            for (int pr = 0; pr < 2; ++pr) {
                const uint32_t bAd = stg + bRow + pr * (16 * 64) + bCh;
                ldsm4(bh[2 * pr][0], bh[2 * pr][1], bh[2 * pr + 1][0], bh[2 * pr + 1][1],
                      bAd + TS2);
                ldsm4(bl[2 * pr][0], bl[2 * pr][1], bl[2 * pr + 1][0], bl[2 * pr + 1][1],
                      bAd + 2 * TS2);
            }
#pragma unroll
            for (int mt = 0; mt < 4; ++mt)
#pragma unroll
                for (int nt = 0; nt < 4; ++nt) mma16816(acc[mt][nt], ah[mt], bh[nt]);
#pragma unroll
            for (int mt = 0; mt < 4; ++mt)
#pragma unroll
                for (int nt = 0; nt < 4; ++nt) mma16816(acc[mt][nt], ah[mt], bl[nt]);
        }
    }

    if (Oh != nullptr) {
        // stage fp16 C tile in smem, then fully-coalesced 16B stores
        __syncthreads();
        __half* ct = (__half*)smem;
#pragma unroll
        for (int mt = 0; mt < 4; ++mt) {
            const int lr = wm * 64 + mt * 16 + gid;
#pragma unroll
            for (int nt = 0; nt < 4; ++nt) {
                const int lc = wn * 32 + nt * 8 + tig * 2;
                *(uint32_t*)&ct[lr * CST + lc] =
                    hpack2(__float2half(acc[mt][nt][0]), __float2half(acc[mt][nt][1]));
                *(uint32_t*)&ct[(lr + 8) * CST + lc] =
                    hpack2(__float2half(acc[mt][nt][2]), __float2half(acc[mt][nt][3]));
            }
        }
        __syncthreads();
        for (int idx = tid; idx < 2048; idx += 256) {
            const int r = idx >> 4, ch = idx & 15;
            const int gr = row0 + r;
            if (gr < M)
                *(uint4*)(Oh + (size_t)gr * N + col0 + ch * 8) =
                    *(const uint4*)&ct[r * CST + ch * 8];
        }
    } else {
#pragma unroll
        for (int mt = 0; mt < 4; ++mt) {
            const int gr = row0 + wm * 64 + mt * 16 + gid;
#pragma unroll
            for (int nt = 0; nt < 4; ++nt) {
                const int gc = col0 + wn * 32 + nt * 8 + tig * 2;
                float b0 = 0.f, b1 = 0.f;
                if (bias) { b0 = __ldg(bias + gc); b1 = __ldg(bias + gc + 1); }
                if (gr < M)
                    *(float2*)(Cc + (size_t)gr * N + gc) =
                        make_float2(acc[mt][nt][0] + b0, acc[mt][nt][1] + b1);
                if (gr + 8 < M)
                    *(float2*)(Cc + (size_t)(gr + 8) * N + gc) =
                        make_float2(acc[mt][nt][2] + b0, acc[mt][nt][3] + b1);
            }
        }
    }
}

// ============================================================================
// Attention MMA helpers: 64x64 fp16 tiles, 128B rows, chunk swizzle c^(row&7)
// ============================================================================
#define ATS 8192   // one 64x64 fp16 tile

template <bool TRANS>
__device__ __forceinline__ void att_mma64(
    float (&acc)[8][4], uint32_t sA, uint32_t sB, int m0, int lane)
{
    const int rA = (lane & 7) + ((lane >> 3) & 1) * 8;
    const int cA = (lane >> 4) & 1;
#pragma unroll
    for (int s = 0; s < 4; ++s) {
        uint32_t a[4];
        {
            const int row = m0 + rA;
            const uint32_t ad = sA + (uint32_t)row * 128u
                              + (uint32_t)(((2 * s + cA) ^ (row & 7)) * 16);
            ldsm4(a[0], a[1], a[2], a[3], ad);
        }
        uint32_t bb[8][2];
#pragma unroll
        for (int p = 0; p < 4; ++p) {
            uint32_t ad;
            if (TRANS) {
                const int row = s * 16 + (lane & 7) + ((lane >> 3) & 1) * 8;
                const int ch  = 2 * p + ((lane >> 4) & 1);
                ad = sB + (uint32_t)row * 128u + (uint32_t)((ch ^ (row & 7)) * 16);
                ldsm4t(bb[2 * p][0], bb[2 * p][1], bb[2 * p + 1][0], bb[2 * p + 1][1], ad);
            } else {
                const int row = p * 16 + (lane & 7) + ((lane >> 4) & 1) * 8;
                const int ch  = 2 * s + ((lane >> 3) & 1);
                ad = sB + (uint32_t)row * 128u + (uint32_t)((ch ^ (row & 7)) * 16);
                ldsm4(bb[2 * p][0], bb[2 * p][1], bb[2 * p + 1][0], bb[2 * p + 1][1], ad);
            }
        }
#pragma unroll
        for (int nt = 0; nt < 8; ++nt) mma16816(acc[nt], a, bb[nt]);
    }
}

#define TILE_LOAD1(T, NMAP, RMAX, GOFF)                                        \
    for (int idx = tid; idx < 512; idx += 128) {                               \
        const int r = idx >> 3, cc = idx & 7;                                  \
        const uint32_t d = (uint32_t)r * 128u + (uint32_t)((cc ^ (r & 7)) * 16); \
        uint4 v = make_uint4(0, 0, 0, 0);                                      \
        if (r < (RMAX)) {                                                      \
            const int n = (NMAP);                                              \
            v = *(const uint4*)(qk + (size_t)n * C3 + (GOFF) + cc * 8);        \
        }                                                                      \
        *(uint4*)((T) + d) = v;                                                \
    }

// ============================================================================
// Phase 1: column scores via fp16 MMA. Block=(w, head, b), 128 threads.
// ============================================================================
__global__ __launch_bounds__(128) void k_colscore(
    const __half* __restrict__ qkv, float* __restrict__ sc)
{
    __shared__ __align__(16) char sm[2 * ATS];
    char* T0 = sm;              // Q
    char* T2 = sm + ATS;        // K
    const int w = blockIdx.x, head = blockIdx.y, b = blockIdx.z;
    const int tid = threadIdx.x, wid = tid >> 5, lane = tid & 31;
    const __half* qk = qkv + (size_t)b * NTOK * C3;
    const int qoff = head * HD;

    TILE_LOAD1(T0, 1 + r * W_ + w, 56, qoff)
    TILE_LOAD1(T2, (r == 0) ? 0 : (1 + (r - 1) * W_ + w), 57, C_ + qoff)
    __syncthreads();

    float acc[8][4];
#pragma unroll
    for (int i = 0; i < 8; ++i)
#pragma unroll
        for (int j = 0; j < 4; ++j) acc[i][j] = 0.f;

    att_mma64<false>(acc, su32(T0), su32(T2), wid * 16, lane);

    float* out = sc + ((((size_t)b * NH_ + head) * H_) * W_ + w) * 64;
    const int crow = wid * 16 + (lane >> 2);
    const int ccol = (lane & 3) * 2;
#pragma unroll
    for (int nt = 0; nt < 8; ++nt)
#pragma unroll
        for (int i = 0; i < 4; ++i) {
            const int row = crow + (i >> 1) * 8;
            const int col = nt * 8 + ccol + (i & 1);
            if (row < 56 && col < 57)
                out[(size_t)row * (W_ * 64) + col] = acc[nt][i] * 0.125f;
        }
}

// ============================================================================
// Phase 2: row scores (MMA) + full softmax + row P·V (MMA).
// ============================================================================
#define PST 132
#define RF_SMEM (2 * ATS + 64 * PST * 4)   // 16384 + 33792 = 50176

__global__ __launch_bounds__(128) void k_rowfused(
    const __half* __restrict__ qkv, float* __restrict__ sc,
    float* __restrict__ attp)
{
    extern __shared__ __align__(16) char dsm[];
    char* T0 = dsm;              // Q -> P(fp16)
    char* T2 = dsm + ATS;        // K -> V
    float* P = (float*)(dsm + 2 * ATS);

    const int h = blockIdx.x, head = blockIdx.y, b = blockIdx.z;
    const int tid = threadIdx.x, wid = tid >> 5, lane = tid & 31;
    const __half* qk = qkv + (size_t)b * NTOK * C3;
    const int qoff = head * HD;
    const int nrow0 = 1 + h * W_;

    TILE_LOAD1(T0, nrow0 + r, 56, qoff)
    TILE_LOAD1(T2, nrow0 + r, 56, C_ + qoff)
    __syncthreads();

    {
        float acc[8][4];
#pragma unroll
        for (int i = 0; i < 8; ++i)
#pragma unroll
            for (int j = 0; j < 4; ++j) acc[i][j] = 0.f;
        att_mma64<false>(acc, su32(T0), su32(T2), wid * 16, lane);

        const int crow = wid * 16 + (lane >> 2);
        const int ccol = (lane & 3) * 2;
#pragma unroll
        for (int nt = 0; nt < 8; ++nt)
#pragma unroll
            for (int i = 0; i < 4; ++i) {
                const int row = crow + (i >> 1) * 8;
                const int col = nt * 8 + ccol + (i & 1);
                float v = acc[nt][i] * 0.125f;
                if (col == row || col >= 56) v = -1e30f;
                P[row * PST + 60 + col] = v;
            }
    }
    __syncthreads();

    {
        const float* scb = sc + ((((size_t)b * NH_ + head) * H_ + h) * W_) * 64;
        for (int idx = tid; idx < 56 * 57; idx += 128) {
            const int q = idx / 57, j = idx % 57;
            P[q * PST + j] = scb[(size_t)q * 64 + j];
        }
    }
    TILE_LOAD1(T2, nrow0 + r, 56, 2 * C_ + qoff)
    __syncthreads();

    if (tid < 56) {
        float* row = P + tid * PST;
        float m = -1e30f;
#pragma unroll 4
        for (int j = 0; j < 57; ++j) m = fmaxf(m, row[j]);
#pragma unroll 4
        for (int j = 60; j < 116; ++j) m = fmaxf(m, row[j]);
        float s = 0.f;
#pragma unroll 4
        for (int j = 0; j < 57; ++j) { float e = __expf(row[j] - m); row[j] = e; s += e; }
#pragma unroll 4
        for (int j = 60; j < 116; ++j) { float e = __expf(row[j] - m); row[j] = e; s += e; }
        const float inv = 1.f / s;
#pragma unroll 4
        for (int j = 0; j < 57; ++j) row[j] *= inv;
#pragma unroll 4
        for (int j = 60; j < 116; ++j) row[j] *= inv;
    }
    __syncthreads();

    {
        float* scb = sc + ((((size_t)b * NH_ + head) * H_ + h) * W_) * 64;
        for (int idx = tid; idx < 56 * 57; idx += 128) {
            const int q = idx / 57, j = idx % 57;
            scb[(size_t)q * 64 + j] = P[q * PST + j];
        }
        for (int idx = tid; idx < 4096; idx += 128) {
            const int q = idx >> 6, k = idx & 63;
            float v = (q < 56 && k < 56) ? P[q * PST + 60 + k] : 0.f;
            const uint32_t d = (uint32_t)q * 128u
                             + (uint32_t)((((k >> 3) ^ (q & 7)) * 16) + (k & 7) * 2);
            *(__half*)(T0 + d) = __float2half(v);
        }
    }
    __syncthreads();

    {
        float acc[8][4];
#pragma unroll
        for (int i = 0; i < 8; ++i)
#pragma unroll
            for (int j = 0; j < 4; ++j) acc[i][j] = 0.f;
        att_mma64<true>(acc, su32(T0), su32(T2), wid * 16, lane);

        const int crow = wid * 16 + (lane >> 2);
        const int ccol = (lane & 3) * 2;
#pragma unroll
        for (int nt = 0; nt < 8; ++nt) {
            const int col = nt * 8 + ccol;
            const int r0 = crow, r1 = crow + 8;
            if (r0 < 56)
                *(float2*)(attp + ((size_t)b * NTOK + nrow0 + r0) * C_ + qoff + col)
                    = make_float2(acc[nt][0], acc[nt][1]);
            if (r1 < 56)
                *(float2*)(attp + ((size_t)b * NTOK + nrow0 + r1) * C_ + qoff + col)
                    = make_float2(acc[nt][2], acc[nt][3]);
        }
    }
}

// ============================================================================
// Phase 3: column aggregation (MMA) + fp16 emit. Block=(w, head, b).
// ============================================================================
__global__ __launch_bounds__(128) void k_colagg(
    const __half* __restrict__ qkv, const float* __restrict__ sc,
    const float* __restrict__ attp, __half* __restrict__ outh)
{
    __shared__ __align__(16) char sm[2 * ATS];
    char* T0 = sm;              // P col (fp16)
    char* T2 = sm + ATS;        // V col
    const int w = blockIdx.x, head = blockIdx.y, b = blockIdx.z;
    const int tid = threadIdx.x, wid = tid >> 5, lane = tid & 31;
    const __half* qk = qkv + (size_t)b * NTOK * C3;
    const int qoff = head * HD;

    TILE_LOAD1(T2, (r == 0) ? 0 : (1 + (r - 1) * W_ + w), 57, 2 * C_ + qoff)
    {
        const float* scb = sc + (((size_t)b * NH_ + head) * H_) * (W_ * 64)
                         + (size_t)w * 64;
        for (int idx = tid; idx < 4096; idx += 128) {
            const int q = idx >> 6, k = idx & 63;
            float v = (q < 56 && k < 57) ? scb[(size_t)q * (W_ * 64) + k] : 0.f;
            const uint32_t d = (uint32_t)q * 128u
                             + (uint32_t)((((k >> 3) ^ (q & 7)) * 16) + (k & 7) * 2);
            *(__half*)(T0 + d) = __float2half(v);
        }
    }
    __syncthreads();

    float acc[8][4];
#pragma unroll
    for (int i = 0; i < 8; ++i)
#pragma unroll
        for (int j = 0; j < 4; ++j) acc[i][j] = 0.f;
    att_mma64<true>(acc, su32(T0), su32(T2), wid * 16, lane);

    const int crow = wid * 16 + (lane >> 2);
    const int ccol = (lane & 3) * 2;
#pragma unroll
    for (int nt = 0; nt < 8; ++nt) {
        const int col = nt * 8 + ccol;
#pragma unroll
        for (int half = 0; half < 2; ++half) {
            const int row = crow + half * 8;
            if (row >= 56) continue;
            const size_t off = ((size_t)b * NTOK + 1 + row * W_ + w) * C_ + qoff + col;
            const float2 rp = *(const float2*)(attp + off);
            *(uint32_t*)(outh + off) =
                hpack2(__float2half(acc[nt][2 * half + 0] + rp.x),
                       __float2half(acc[nt][2 * half + 1] + rp.y));
        }
    }
}

// ---------------- CLS-token attention: split-K partials + reduce ------------
__global__ __launch_bounds__(256) void cls_part(
    const __half* __restrict__ qkv, float* __restrict__ clsp)
{
    const int nh = blockIdx.x, b = blockIdx.y, ch = blockIdx.z;
    const int tid = threadIdx.x;
    const int n0 = ch * KC;
    const int n1 = min(NTOK, n0 + KC);
    const int cnt = n1 - n0;

    __shared__ float qs[HD];
    __shared__ float scs[KC];
    __shared__ float red[256];
    __shared__ float part[4][HD];

    const __half* base = qkv + (size_t)b * NTOK * C3;
    if (tid < HD) qs[tid] = __half2float(base[nh * HD + tid]);
    __syncthreads();

    for (int i = tid; i < cnt; i += 256) {
        const __half2* kp = (const __half2*)(base + (size_t)(n0 + i) * C3 + C_ + nh * HD);
        float s = 0.f;
#pragma unroll
        for (int d = 0; d < HD / 2; ++d) {
            float2 kv = __half22float2(kp[d]);
            s += qs[2 * d] * kv.x + qs[2 * d + 1] * kv.y;
        }
        scs[i] = s * 0.125f;
    }
    __syncthreads();

    float m = -1e30f;
    for (int i = tid; i < cnt; i += 256) m = fmaxf(m, scs[i]);
    red[tid] = m;
    __syncthreads();
    for (int st = 128; st; st >>= 1) {
        if (tid < st) red[tid] = fmaxf(red[tid], red[tid + st]);
        __syncthreads();
    }
    m = red[0];
    __syncthreads();

    float s = 0.f;
    for (int i = tid; i < cnt; i += 256) {
        float e = __expf(scs[i] - m);
        scs[i] = e;
        s += e;
    }
    red[tid] = s;
    __syncthreads();
    for (int st = 128; st; st >>= 1) {
        if (tid < st) red[tid] += red[tid + st];
        __syncthreads();
    }
    const float S = red[0];
    __syncthreads();

    const int d = tid & 63, kq = tid >> 6;
    float acc = 0.f;
    for (int i = kq; i < cnt; i += 4)
        acc += scs[i] * __half2float(base[(size_t)(n0 + i) * C3 + 2 * C_ + nh * HD + d]);
    part[kq][d] = acc;
    __syncthreads();
    if (kq == 0) {
        float* o = clsp + ((size_t)(b * NH_ + nh) * NCH + ch) * 66;
        o[d] = part[0][d] + part[1][d] + part[2][d] + part[3][d];
        if (d == 0) { o[64] = m; o[65] = S; }
    }
}

__global__ __launch_bounds__(64) void cls_reduce(
    const float* __restrict__ clsp, __half* __restrict__ outh)
{
    const int nh = blockIdx.x, b = blockIdx.y;
    const int d = threadIdx.x;
    const float* o = clsp + (size_t)(b * NH_ + nh) * NCH * 66;
    float M = -1e30f;
#pragma unroll
    for (int c = 0; c < NCH; ++c) M = fmaxf(M, o[c * 66 + 64]);
    float S = 0.f, A = 0.f;
#pragma unroll
    for (int c = 0; c < NCH; ++c) {
        const float wgt = __expf(o[c * 66 + 64] - M);
        S += o[c * 66 + 65] * wgt;
        A += o[c * 66 + d] * wgt;
    }
    outh[(size_t)b * NTOK * C_ + nh * HD + d] = __float2half(A / S);
}

// ---------------------------------------------------------------------------
extern "C" void kernel_launch(void* const* d_in, const int* in_sizes, int n_in,
                              void* d_out, int out_size)
{
    const float* x     = (const float*)d_in[0];
    const float* Wqkv  = (const float*)d_in[1];
    const float* Wproj = (const float*)d_in[2];
    const float* bproj = (const float*)d_in[3];
    float* out = (float*)d_out;

    float *att, *sc, *clsp;
    __half *qkv, *xh, *ath, *wqh, *wql, *wph, *wpl;
    cudaGetSymbolAddress((void**)&qkv,  g_qkv);
    cudaGetSymbolAddress((void**)&att,  g_att);
    cudaGetSymbolAddress((void**)&sc,   g_sc);
    cudaGetSymbolAddress((void**)&clsp, g_clsp);
    cudaGetSymbolAddress((void**)&xh,   g_xh);
    cudaGetSymbolAddress((void**)&ath,  g_ath);
    cudaGetSymbolAddress((void**)&wqh,  g_wqh);
    cudaGetSymbolAddress((void**)&wql,  g_wql);
    cudaGetSymbolAddress((void**)&wph,  g_wph);
    cudaGetSymbolAddress((void**)&wpl,  g_wpl);

    cudaFuncSetAttribute(gemm_mma,
                         cudaFuncAttributeMaxDynamicSharedMemorySize, GEMM_SMEM);
    cudaFuncSetAttribute(k_rowfused,
                         cudaFuncAttributeMaxDynamicSharedMemorySize, RF_SMEM);

    // 0) pre-passes
    {
        int n4 = MTOT * C_ / 4;
        k_split<<<(n4 + 255) / 256, 256>>>(x, xh, n4);
        k_tsplit<<<dim3(C3 / 32, C_ / 32), dim3(32, 8)>>>(Wqkv,  wqh, wql, C_, C3);
        k_tsplit<<<dim3(C_ / 32, C_ / 32), dim3(32, 8)>>>(Wproj, wph, wpl, C_, C_);
    }
    // 1) QKV projection -> fp16 qkv (smem-staged coalesced epilogue)
    gemm_mma<<<dim3(C3 / 128, (MTOT + 127) / 128), 256, GEMM_SMEM>>>(
        xh, wqh, wql, nullptr, nullptr, qkv, MTOT, C3);
    // 2) attention phases (fp16 MMA)
    {
        dim3 ag(W_, NH_, B_);
        k_colscore<<<ag, 128>>>(qkv, sc);
        dim3 rg(H_, NH_, B_);
        k_rowfused<<<rg, 128, RF_SMEM>>>(qkv, sc, att);
        cls_part<<<dim3(NH_, B_, NCH), 256>>>(qkv, clsp);
        cls_reduce<<<dim3(NH_, B_), 64>>>(clsp, ath);
        k_colagg<<<ag, 128>>>(qkv, sc, att, ath);
    }
    // 3) output projection + bias (fp32 out)
    gemm_mma<<<dim3(C_ / 128, (MTOT + 127) / 128), 256, GEMM_SMEM>>>(
        ath, wph, wpl, out, bproj, nullptr, MTOT, C_);
}

// round 16
// speedup vs baseline: 1.4889x; 1.0084x over previous
#include <cuda_runtime.h>
#include <cuda_fp16.h>
#include <cstdint>

#define H_    56
#define W_    56
#define NH_   12
#define HD    64
#define NTOK  3137          // 56*56 + 1
#define C_    768
#define C3    2304
#define B_    8
#define MTOT  (B_ * NTOK)   // 25096
#define KDIM  768
#define BK    32
#define NSTG  (KDIM / BK)   // 24
#define NCH   8
#define KC    393           // ceil(NTOK / NCH)

typedef unsigned long long u64;

// ---------------- scratch (__device__ globals; no cudaMalloc allowed) -------
__device__ __half g_qkv[(size_t)MTOT * C3];   // fp16 QKV activations
__device__ __half g_att[(size_t)MTOT * C_];   // fp16 row-partial
__device__ __half g_sc [(size_t)B_ * NH_ * H_ * W_ * 64]; // col scores/probs fp16
__device__ float  g_clsp[(size_t)B_ * NH_ * NCH * 66];    // cls partials
__device__ __half g_xh [(size_t)MTOT * C_];   // x in fp16
__device__ __half g_ath[(size_t)MTOT * C_];   // attention out fp16
__device__ __half g_wqh[(size_t)C3 * C_];     // W_qkv^T split  [N,K]
__device__ __half g_wql[(size_t)C3 * C_];
__device__ __half g_wph[(size_t)C_ * C_];     // W_proj^T split [N,K]
__device__ __half g_wpl[(size_t)C_ * C_];

__device__ __forceinline__ void hsplit2(float v, __half& h, __half& l) {
    h = __float2half(v);
    l = __float2half(v - __half2float(h));
}
__device__ __forceinline__ uint32_t hpack2(__half a, __half b) {
    return (uint32_t)__half_as_ushort(a) |
           ((uint32_t)__half_as_ushort(b) << 16);
}
__device__ __forceinline__ uint32_t su32(const void* p) {
    uint32_t a;
    asm("{ .reg .u64 t; cvta.to.shared.u64 t, %1; cvt.u32.u64 %0, t; }"
        : "=r"(a) : "l"(p));
    return a;
}
__device__ __forceinline__ void cp16(uint32_t dst, const void* src, bool ok) {
    int sz = ok ? 16 : 0;
    asm volatile("cp.async.cg.shared.global [%0], [%1], 16, %2;"
                 :: "r"(dst), "l"(src), "r"(sz) : "memory");
}
__device__ __forceinline__ void mma16816(float* c, const uint32_t* a, const uint32_t* b) {
    asm volatile(
        "mma.sync.aligned.m16n8k16.row.col.f32.f16.f16.f32 "
        "{%0,%1,%2,%3}, {%4,%5,%6,%7}, {%8,%9}, {%0,%1,%2,%3};"
        : "+f"(c[0]), "+f"(c[1]), "+f"(c[2]), "+f"(c[3])
        : "r"(a[0]), "r"(a[1]), "r"(a[2]), "r"(a[3]), "r"(b[0]), "r"(b[1]));
}
__device__ __forceinline__ void ldsm4(uint32_t& r0, uint32_t& r1, uint32_t& r2,
                                      uint32_t& r3, uint32_t addr) {
    asm volatile("ldmatrix.sync.aligned.m8n8.x4.shared.b16 {%0,%1,%2,%3}, [%4];"
                 : "=r"(r0), "=r"(r1), "=r"(r2), "=r"(r3) : "r"(addr));
}
__device__ __forceinline__ void ldsm4t(uint32_t& r0, uint32_t& r1, uint32_t& r2,
                                       uint32_t& r3, uint32_t addr) {
    asm volatile("ldmatrix.sync.aligned.m8n8.x4.trans.shared.b16 {%0,%1,%2,%3}, [%4];"
                 : "=r"(r0), "=r"(r1), "=r"(r2), "=r"(r3) : "r"(addr));
}

// ---------------- pre-pass: fp32 -> fp16 ------------------------------------
__global__ __launch_bounds__(256) void k_split(
    const float* __restrict__ in, __half* __restrict__ hi, int n4)
{
    int i = blockIdx.x * 256 + threadIdx.x;
    if (i >= n4) return;
    float4 v = ((const float4*)in)[i];
    __half hv[4];
    hv[0] = __float2half(v.x);
    hv[1] = __float2half(v.y);
    hv[2] = __float2half(v.z);
    hv[3] = __float2half(v.w);
    ((uint2*)hi)[i] = *(uint2*)hv;
}

// ---------------- pre-pass: transpose + fp16 split weights ------------------
__global__ __launch_bounds__(256) void k_tsplit(
    const float* __restrict__ W, __half* __restrict__ th,
    __half* __restrict__ tl, int R, int Cn)
{
    __shared__ float t[32][33];
    int x = blockIdx.x * 32 + threadIdx.x;
    int y = blockIdx.y * 32 + threadIdx.y;
#pragma unroll
    for (int j = 0; j < 32; j += 8)
        t[threadIdx.y + j][threadIdx.x] = W[(size_t)(y + j) * Cn + x];
    __syncthreads();
    int ox = blockIdx.y * 32 + threadIdx.x;
    int oy = blockIdx.x * 32 + threadIdx.y;
#pragma unroll
    for (int j = 0; j < 32; j += 8) {
        float v = t[threadIdx.x][threadIdx.y + j];
        __half h, l;
        hsplit2(v, h, l);
        th[(size_t)(oy + j) * R + ox] = h;
        tl[(size_t)(oy + j) * R + ox] = l;
    }
}

// ---------------- fp16x2 GEMM: C = Ah[M,K] @ (Bh+Bl)[N,K]^T -----------------
// 4-stage pipeline; fp32 out (+bias) when Oh==null, else smem-staged fp16 out.
#define TS2     8192
#define STG2    (3 * TS2)             // 24 KB per stage
#define GEMM_SMEM (4 * STG2)          // 96 KB
#define CST     136                   // C-tile smem row stride in halves

__global__ __launch_bounds__(256) void gemm_mma(
    const __half* __restrict__ Ah,
    const __half* __restrict__ Bh, const __half* __restrict__ Bl,
    float* __restrict__ Cc, const float* __restrict__ bias,
    __half* __restrict__ Oh, int M, int N)
{
    extern __shared__ __align__(128) char smem[];
    const uint32_t sb = su32(smem);
    const int tid  = threadIdx.x;
    const int wid  = tid >> 5, lane = tid & 31;
    const int gid  = lane >> 2, tig = lane & 3;
    const int wm   = wid & 1, wn = wid >> 1;
    const int row0 = blockIdx.y * 128, col0 = blockIdx.x * 128;

    float acc[4][4][4];
#pragma unroll
    for (int i = 0; i < 4; ++i)
#pragma unroll
        for (int j = 0; j < 4; ++j)
#pragma unroll
            for (int k = 0; k < 4; ++k) acc[i][j][k] = 0.f;

    const int rlA = (lane & 7) + ((lane >> 3) & 1) * 8;
    const int kcA = (lane >> 4) & 1;
    const int swA = (rlA >> 1) & 3;
    const int rlB = (lane & 7) + ((lane >> 4) & 1) * 8;
    const int kcB = (lane >> 3) & 1;
    const int swB = (rlB >> 1) & 3;
    const uint32_t aRow = (uint32_t)(wm * 64 + rlA) * 64u;
    const uint32_t bRow = (uint32_t)(wn * 32 + rlB) * 64u;

    const int r0c = tid >> 2, j0c = tid & 3;
    const int r1c = (tid + 256) >> 2, j1c = tid & 3;

    auto issue = [&](int c) {
        const int k0 = c * BK;
        const uint32_t stg = sb + (uint32_t)(c & 3) * STG2;
#pragma unroll
        for (int rep = 0; rep < 2; ++rep) {
            const int row = rep ? r1c : r0c;
            const int j   = rep ? j1c : j0c;
            const uint32_t d = stg + (uint32_t)row * 64u
                             + (uint32_t)((j ^ ((row >> 1) & 3)) * 16);
            const int grA = row0 + row;
            const bool okA = grA < M;
            const size_t aoff = (size_t)(okA ? grA : 0) * KDIM + k0 + j * 8;
            cp16(d, Ah + aoff, okA);
            const size_t boff = (size_t)(col0 + row) * KDIM + k0 + j * 8;
            cp16(d + TS2,     Bh + boff, true);
            cp16(d + 2 * TS2, Bl + boff, true);
        }
        asm volatile("cp.async.commit_group;" ::: "memory");
    };

    issue(0);
    issue(1);
    issue(2);

    for (int c = 0; c < NSTG; ++c) {
        if (c + 2 < NSTG)
            asm volatile("cp.async.wait_group 2;" ::: "memory");
        else if (c + 1 < NSTG)
            asm volatile("cp.async.wait_group 1;" ::: "memory");
        else
            asm volatile("cp.async.wait_group 0;" ::: "memory");
        __syncthreads();
        if (c + 3 < NSTG) issue(c + 3);

        const uint32_t stg = sb + (uint32_t)(c & 3) * STG2;

#pragma unroll
        for (int kk = 0; kk < 2; ++kk) {
            const uint32_t aCh = (uint32_t)(((kcA + 2 * kk) ^ swA) * 16);
            const uint32_t bCh = (uint32_t)(((kcB + 2 * kk) ^ swB) * 16);
            uint32_t ah[4][4], bh[4][2], bl[4][2];
#pragma unroll
            for (int mt = 0; mt < 4; ++mt) {
                const uint32_t aAd = stg + aRow + mt * (16 * 64) + aCh;
                ldsm4(ah[mt][0], ah[mt][1], ah[mt][2], ah[mt][3], aAd);
            }
#pragma unroll
            for (int pr = 0; pr < 2; ++pr) {
                const uint32_t bAd = stg + bRow + pr * (16 * 64) + bCh;
                ldsm4(bh[2 * pr][0], bh[2 * pr][1], bh[2 * pr + 1][0], bh[2 * pr + 1][1],
                      bAd + TS2);
                ldsm4(bl[2 * pr][0], bl[2 * pr][1], bl[2 * pr + 1][0], bl[2 * pr + 1][1],
                      bAd + 2 * TS2);
            }
#pragma unroll
            for (int mt = 0; mt < 4; ++mt)
#pragma unroll
                for (int nt = 0; nt < 4; ++nt) mma16816(acc[mt][nt], ah[mt], bh[nt]);
#pragma unroll
            for (int mt = 0; mt < 4; ++mt)
#pragma unroll
                for (int nt = 0; nt < 4; ++nt) mma16816(acc[mt][nt], ah[mt], bl[nt]);
        }
    }

    if (Oh != nullptr) {
        // stage fp16 C tile in smem, then fully-coalesced 16B stores
        __syncthreads();
        __half* ct = (__half*)smem;
#pragma unroll
        for (int mt = 0; mt < 4; ++mt) {
            const int lr = wm * 64 + mt * 16 + gid;
#pragma unroll
            for (int nt = 0; nt < 4; ++nt) {
                const int lc = wn * 32 + nt * 8 + tig * 2;
                *(uint32_t*)&ct[lr * CST + lc] =
                    hpack2(__float2half(acc[mt][nt][0]), __float2half(acc[mt][nt][1]));
                *(uint32_t*)&ct[(lr + 8) * CST + lc] =
                    hpack2(__float2half(acc[mt][nt][2]), __float2half(acc[mt][nt][3]));
            }
        }
        __syncthreads();
        for (int idx = tid; idx < 2048; idx += 256) {
            const int r = idx >> 4, ch = idx & 15;
            const int gr = row0 + r;
            if (gr < M)
                *(uint4*)(Oh + (size_t)gr * N + col0 + ch * 8) =
                    *(const uint4*)&ct[r * CST + ch * 8];
        }
    } else {
#pragma unroll
        for (int mt = 0; mt < 4; ++mt) {
            const int gr = row0 + wm * 64 + mt * 16 + gid;
#pragma unroll
            for (int nt = 0; nt < 4; ++nt) {
                const int gc = col0 + wn * 32 + nt * 8 + tig * 2;
                float b0 = 0.f, b1 = 0.f;
                if (bias) { b0 = __ldg(bias + gc); b1 = __ldg(bias + gc + 1); }
                if (gr < M)
                    *(float2*)(Cc + (size_t)gr * N + gc) =
                        make_float2(acc[mt][nt][0] + b0, acc[mt][nt][1] + b1);
                if (gr + 8 < M)
                    *(float2*)(Cc + (size_t)(gr + 8) * N + gc) =
                        make_float2(acc[mt][nt][2] + b0, acc[mt][nt][3] + b1);
            }
        }
    }
}

// ============================================================================
// Attention MMA helpers: 64x64 fp16 tiles, 128B rows, chunk swizzle c^(row&7)
// ============================================================================
#define ATS 8192   // one 64x64 fp16 tile

template <bool TRANS>
__device__ __forceinline__ void att_mma64(
    float (&acc)[8][4], uint32_t sA, uint32_t sB, int m0, int lane)
{
    const int rA = (lane & 7) + ((lane >> 3) & 1) * 8;
    const int cA = (lane >> 4) & 1;
#pragma unroll
    for (int s = 0; s < 4; ++s) {
        uint32_t a[4];
        {
            const int row = m0 + rA;
            const uint32_t ad = sA + (uint32_t)row * 128u
                              + (uint32_t)(((2 * s + cA) ^ (row & 7)) * 16);
            ldsm4(a[0], a[1], a[2], a[3], ad);
        }
        uint32_t bb[8][2];
#pragma unroll
        for (int p = 0; p < 4; ++p) {
            uint32_t ad;
            if (TRANS) {
                const int row = s * 16 + (lane & 7) + ((lane >> 3) & 1) * 8;
                const int ch  = 2 * p + ((lane >> 4) & 1);
                ad = sB + (uint32_t)row * 128u + (uint32_t)((ch ^ (row & 7)) * 16);
                ldsm4t(bb[2 * p][0], bb[2 * p][1], bb[2 * p + 1][0], bb[2 * p + 1][1], ad);
            } else {
                const int row = p * 16 + (lane & 7) + ((lane >> 4) & 1) * 8;
                const int ch  = 2 * s + ((lane >> 3) & 1);
                ad = sB + (uint32_t)row * 128u + (uint32_t)((ch ^ (row & 7)) * 16);
                ldsm4(bb[2 * p][0], bb[2 * p][1], bb[2 * p + 1][0], bb[2 * p + 1][1], ad);
            }
        }
#pragma unroll
        for (int nt = 0; nt < 8; ++nt) mma16816(acc[nt], a, bb[nt]);
    }
}

#define TILE_LOAD1(T, NMAP, RMAX, GOFF)                                        \
    for (int idx = tid; idx < 512; idx += 128) {                               \
        const int r = idx >> 3, cc = idx & 7;                                  \
        const uint32_t d = (uint32_t)r * 128u + (uint32_t)((cc ^ (r & 7)) * 16); \
        uint4 v = make_uint4(0, 0, 0, 0);                                      \
        if (r < (RMAX)) {                                                      \
            const int n = (NMAP);                                              \
            v = *(const uint4*)(qk + (size_t)n * C3 + (GOFF) + cc * 8);        \
        }                                                                      \
        *(uint4*)((T) + d) = v;                                                \
    }

// ============================================================================
// Phase 1: column scores via fp16 MMA. Block=(w, head, b), 128 threads.
// ============================================================================
__global__ __launch_bounds__(128) void k_colscore(
    const __half* __restrict__ qkv, __half* __restrict__ sc)
{
    __shared__ __align__(16) char sm[2 * ATS];
    char* T0 = sm;              // Q
    char* T2 = sm + ATS;        // K
    const int w = blockIdx.x, head = blockIdx.y, b = blockIdx.z;
    const int tid = threadIdx.x, wid = tid >> 5, lane = tid & 31;
    const __half* qk = qkv + (size_t)b * NTOK * C3;
    const int qoff = head * HD;

    TILE_LOAD1(T0, 1 + r * W_ + w, 56, qoff)
    TILE_LOAD1(T2, (r == 0) ? 0 : (1 + (r - 1) * W_ + w), 57, C_ + qoff)
    __syncthreads();

    float acc[8][4];
#pragma unroll
    for (int i = 0; i < 8; ++i)
#pragma unroll
        for (int j = 0; j < 4; ++j) acc[i][j] = 0.f;

    att_mma64<false>(acc, su32(T0), su32(T2), wid * 16, lane);

    __half* out = sc + ((((size_t)b * NH_ + head) * H_) * W_ + w) * 64;
    const int crow = wid * 16 + (lane >> 2);
    const int ccol = (lane & 3) * 2;
#pragma unroll
    for (int nt = 0; nt < 8; ++nt)
#pragma unroll
        for (int i = 0; i < 4; ++i) {
            const int row = crow + (i >> 1) * 8;
            const int col = nt * 8 + ccol + (i & 1);
            if (row < 56 && col < 57)
                out[(size_t)row * (W_ * 64) + col] = __float2half(acc[nt][i] * 0.125f);
        }
}

// ============================================================================
// Phase 2: row scores (MMA) + full softmax + row P·V (MMA).
// ============================================================================
#define PST 132
#define RF_SMEM (2 * ATS + 64 * PST * 4)   // 16384 + 33792 = 50176

__global__ __launch_bounds__(128) void k_rowfused(
    const __half* __restrict__ qkv, __half* __restrict__ sc,
    __half* __restrict__ attp)
{
    extern __shared__ __align__(16) char dsm[];
    char* T0 = dsm;              // Q -> P(fp16)
    char* T2 = dsm + ATS;        // K -> V
    float* P = (float*)(dsm + 2 * ATS);

    const int h = blockIdx.x, head = blockIdx.y, b = blockIdx.z;
    const int tid = threadIdx.x, wid = tid >> 5, lane = tid & 31;
    const __half* qk = qkv + (size_t)b * NTOK * C3;
    const int qoff = head * HD;
    const int nrow0 = 1 + h * W_;

    TILE_LOAD1(T0, nrow0 + r, 56, qoff)
    TILE_LOAD1(T2, nrow0 + r, 56, C_ + qoff)
    __syncthreads();

    {
        float acc[8][4];
#pragma unroll
        for (int i = 0; i < 8; ++i)
#pragma unroll
            for (int j = 0; j < 4; ++j) acc[i][j] = 0.f;
        att_mma64<false>(acc, su32(T0), su32(T2), wid * 16, lane);

        const int crow = wid * 16 + (lane >> 2);
        const int ccol = (lane & 3) * 2;
#pragma unroll
        for (int nt = 0; nt < 8; ++nt)
#pragma unroll
            for (int i = 0; i < 4; ++i) {
                const int row = crow + (i >> 1) * 8;
                const int col = nt * 8 + ccol + (i & 1);
                float v = acc[nt][i] * 0.125f;
                if (col == row || col >= 56) v = -1e30f;
                P[row * PST + 60 + col] = v;
            }
    }
    __syncthreads();

    {
        const __half* scb = sc + ((((size_t)b * NH_ + head) * H_ + h) * W_) * 64;
        for (int idx = tid; idx < 56 * 57; idx += 128) {
            const int q = idx / 57, j = idx % 57;
            P[q * PST + j] = __half2float(scb[(size_t)q * 64 + j]);
        }
    }
    TILE_LOAD1(T2, nrow0 + r, 56, 2 * C_ + qoff)
    __syncthreads();

    if (tid < 56) {
        float* row = P + tid * PST;
        float m = -1e30f;
#pragma unroll 4
        for (int j = 0; j < 57; ++j) m = fmaxf(m, row[j]);
#pragma unroll 4
        for (int j = 60; j < 116; ++j) m = fmaxf(m, row[j]);
        float s = 0.f;
#pragma unroll 4
        for (int j = 0; j < 57; ++j) { float e = __expf(row[j] - m); row[j] = e; s += e; }
#pragma unroll 4
        for (int j = 60; j < 116; ++j) { float e = __expf(row[j] - m); row[j] = e; s += e; }
        const float inv = 1.f / s;
#pragma unroll 4
        for (int j = 0; j < 57; ++j) row[j] *= inv;
#pragma unroll 4
        for (int j = 60; j < 116; ++j) row[j] *= inv;
    }
    __syncthreads();

    {
        __half* scb = sc + ((((size_t)b * NH_ + head) * H_ + h) * W_) * 64;
        for (int idx = tid; idx < 56 * 57; idx += 128) {
            const int q = idx / 57, j = idx % 57;
            scb[(size_t)q * 64 + j] = __float2half(P[q * PST + j]);
        }
        for (int idx = tid; idx < 4096; idx += 128) {
            const int q = idx >> 6, k = idx & 63;
            float v = (q < 56 && k < 56) ? P[q * PST + 60 + k] : 0.f;
            const uint32_t d = (uint32_t)q * 128u
                             + (uint32_t)((((k >> 3) ^ (q & 7)) * 16) + (k & 7) * 2);
            *(__half*)(T0 + d) = __float2half(v);
        }
    }
    __syncthreads();

    {
        float acc[8][4];
#pragma unroll
        for (int i = 0; i < 8; ++i)
#pragma unroll
            for (int j = 0; j < 4; ++j) acc[i][j] = 0.f;
        att_mma64<true>(acc, su32(T0), su32(T2), wid * 16, lane);

        const int crow = wid * 16 + (lane >> 2);
        const int ccol = (lane & 3) * 2;
#pragma unroll
        for (int nt = 0; nt < 8; ++nt) {
            const int col = nt * 8 + ccol;
            const int r0 = crow, r1 = crow + 8;
            if (r0 < 56)
                *(uint32_t*)(attp + ((size_t)b * NTOK + nrow0 + r0) * C_ + qoff + col)
                    = hpack2(__float2half(acc[nt][0]), __float2half(acc[nt][1]));
            if (r1 < 56)
                *(uint32_t*)(attp + ((size_t)b * NTOK + nrow0 + r1) * C_ + qoff + col)
                    = hpack2(__float2half(acc[nt][2]), __float2half(acc[nt][3]));
        }
    }
}

// ============================================================================
// Phase 3: column aggregation (MMA) + fp16 emit. Block=(w, head, b).
// ============================================================================
__global__ __launch_bounds__(128) void k_colagg(
    const __half* __restrict__ qkv, const __half* __restrict__ sc,
    const __half* __restrict__ attp, __half* __restrict__ outh)
{
    __shared__ __align__(16) char sm[2 * ATS];
    char* T0 = sm;              // P col (fp16)
    char* T2 = sm + ATS;        // V col
    const int w = blockIdx.x, head = blockIdx.y, b = blockIdx.z;
    const int tid = threadIdx.x, wid = tid >> 5, lane = tid & 31;
    const __half* qk = qkv + (size_t)b * NTOK * C3;
    const int qoff = head * HD;

    TILE_LOAD1(T2, (r == 0) ? 0 : (1 + (r - 1) * W_ + w), 57, 2 * C_ + qoff)
    {
        const __half* scb = sc + (((size_t)b * NH_ + head) * H_) * (W_ * 64)
                          + (size_t)w * 64;
        for (int idx = tid; idx < 4096; idx += 128) {
            const int q = idx >> 6, k = idx & 63;
            __half v = (q < 56 && k < 57) ? scb[(size_t)q * (W_ * 64) + k]
                                          : __float2half(0.f);
            const uint32_t d = (uint32_t)q * 128u
                             + (uint32_t)((((k >> 3) ^ (q & 7)) * 16) + (k & 7) * 2);
            *(__half*)(T0 + d) = v;
        }
    }
    __syncthreads();

    float acc[8][4];
#pragma unroll
    for (int i = 0; i < 8; ++i)
#pragma unroll
        for (int j = 0; j < 4; ++j) acc[i][j] = 0.f;
    att_mma64<true>(acc, su32(T0), su32(T2), wid * 16, lane);

    const int crow = wid * 16 + (lane >> 2);
    const int ccol = (lane & 3) * 2;
#pragma unroll
    for (int nt = 0; nt < 8; ++nt) {
        const int col = nt * 8 + ccol;
#pragma unroll
        for (int half = 0; half < 2; ++half) {
            const int row = crow + half * 8;
            if (row >= 56) continue;
            const size_t off = ((size_t)b * NTOK + 1 + row * W_ + w) * C_ + qoff + col;
            const float2 rp = __half22float2(*(const __half2*)(attp + off));
            *(uint32_t*)(outh + off) =
                hpack2(__float2half(acc[nt][2 * half + 0] + rp.x),
                       __float2half(acc[nt][2 * half + 1] + rp.y));
        }
    }
}

// ---------------- CLS-token attention: split-K partials + reduce ------------
__global__ __launch_bounds__(256) void cls_part(
    const __half* __restrict__ qkv, float* __restrict__ clsp)
{
    const int nh = blockIdx.x, b = blockIdx.y, ch = blockIdx.z;
    const int tid = threadIdx.x;
    const int n0 = ch * KC;
    const int n1 = min(NTOK, n0 + KC);
    const int cnt = n1 - n0;

    __shared__ float qs[HD];
    __shared__ float scs[KC];
    __shared__ float red[256];
    __shared__ float part[4][HD];

    const __half* base = qkv + (size_t)b * NTOK * C3;
    if (tid < HD) qs[tid] = __half2float(base[nh * HD + tid]);
    __syncthreads();

    for (int i = tid; i < cnt; i += 256) {
        const __half2* kp = (const __half2*)(base + (size_t)(n0 + i) * C3 + C_ + nh * HD);
        float s = 0.f;
#pragma unroll
        for (int d = 0; d < HD / 2; ++d) {
            float2 kv = __half22float2(kp[d]);
            s += qs[2 * d] * kv.x + qs[2 * d + 1] * kv.y;
        }
        scs[i] = s * 0.125f;
    }
    __syncthreads();

    float m = -1e30f;
    for (int i = tid; i < cnt; i += 256) m = fmaxf(m, scs[i]);
    red[tid] = m;
    __syncthreads();
    for (int st = 128; st; st >>= 1) {
        if (tid < st) red[tid] = fmaxf(red[tid], red[tid + st]);
        __syncthreads();
    }
    m = red[0];
    __syncthreads();

    float s = 0.f;
    for (int i = tid; i < cnt; i += 256) {
        float e = __expf(scs[i] - m);
        scs[i] = e;
        s += e;
    }
    red[tid] = s;
    __syncthreads();
    for (int st = 128; st; st >>= 1) {
        if (tid < st) red[tid] += red[tid + st];
        __syncthreads();
    }
    const float S = red[0];
    __syncthreads();

    const int d = tid & 63, kq = tid >> 6;
    float acc = 0.f;
    for (int i = kq; i < cnt; i += 4)
        acc += scs[i] * __half2float(base[(size_t)(n0 + i) * C3 + 2 * C_ + nh * HD + d]);
    part[kq][d] = acc;
    __syncthreads();
    if (kq == 0) {
        float* o = clsp + ((size_t)(b * NH_ + nh) * NCH + ch) * 66;
        o[d] = part[0][d] + part[1][d] + part[2][d] + part[3][d];
        if (d == 0) { o[64] = m; o[65] = S; }
    }
}

__global__ __launch_bounds__(64) void cls_reduce(
    const float* __restrict__ clsp, __half* __restrict__ outh)
{
    const int nh = blockIdx.x, b = blockIdx.y;
    const int d = threadIdx.x;
    const float* o = clsp + (size_t)(b * NH_ + nh) * NCH * 66;
    float M = -1e30f;
#pragma unroll
    for (int c = 0; c < NCH; ++c) M = fmaxf(M, o[c * 66 + 64]);
    float S = 0.f, A = 0.f;
#pragma unroll
    for (int c = 0; c < NCH; ++c) {
        const float wgt = __expf(o[c * 66 + 64] - M);
        S += o[c * 66 + 65] * wgt;
        A += o[c * 66 + d] * wgt;
    }
    outh[(size_t)b * NTOK * C_ + nh * HD + d] = __float2half(A / S);
}

// ---------------------------------------------------------------------------
extern "C" void kernel_launch(void* const* d_in, const int* in_sizes, int n_in,
                              void* d_out, int out_size)
{
    const float* x     = (const float*)d_in[0];
    const float* Wqkv  = (const float*)d_in[1];
    const float* Wproj = (const float*)d_in[2];
    const float* bproj = (const float*)d_in[3];
    float* out = (float*)d_out;

    float *clsp;
    __half *qkv, *att, *sc, *xh, *ath, *wqh, *wql, *wph, *wpl;
    cudaGetSymbolAddress((void**)&qkv,  g_qkv);
    cudaGetSymbolAddress((void**)&att,  g_att);
    cudaGetSymbolAddress((void**)&sc,   g_sc);
    cudaGetSymbolAddress((void**)&clsp, g_clsp);
    cudaGetSymbolAddress((void**)&xh,   g_xh);
    cudaGetSymbolAddress((void**)&ath,  g_ath);
    cudaGetSymbolAddress((void**)&wqh,  g_wqh);
    cudaGetSymbolAddress((void**)&wql,  g_wql);
    cudaGetSymbolAddress((void**)&wph,  g_wph);
    cudaGetSymbolAddress((void**)&wpl,  g_wpl);

    cudaFuncSetAttribute(gemm_mma,
                         cudaFuncAttributeMaxDynamicSharedMemorySize, GEMM_SMEM);
    cudaFuncSetAttribute(k_rowfused,
                         cudaFuncAttributeMaxDynamicSharedMemorySize, RF_SMEM);

    // 0) pre-passes
    {
        int n4 = MTOT * C_ / 4;
        k_split<<<(n4 + 255) / 256, 256>>>(x, xh, n4);
        k_tsplit<<<dim3(C3 / 32, C_ / 32), dim3(32, 8)>>>(Wqkv,  wqh, wql, C_, C3);
        k_tsplit<<<dim3(C_ / 32, C_ / 32), dim3(32, 8)>>>(Wproj, wph, wpl, C_, C_);
    }
    // 1) QKV projection -> fp16 qkv (4-stage pipeline, staged epilogue)
    gemm_mma<<<dim3(C3 / 128, (MTOT + 127) / 128), 256, GEMM_SMEM>>>(
        xh, wqh, wql, nullptr, nullptr, qkv, MTOT, C3);
    // 2) attention phases (fp16 MMA, fp16 scratch)
    {
        dim3 ag(W_, NH_, B_);
        k_colscore<<<ag, 128>>>(qkv, sc);
        dim3 rg(H_, NH_, B_);
        k_rowfused<<<rg, 128, RF_SMEM>>>(qkv, sc, att);
        cls_part<<<dim3(NH_, B_, NCH), 256>>>(qkv, clsp);
        cls_reduce<<<dim3(NH_, B_), 64>>>(clsp, ath);
        k_colagg<<<ag, 128>>>(qkv, sc, att, ath);
    }
    // 3) output projection + bias (fp32 out)
    gemm_mma<<<dim3(C_ / 128, (MTOT + 127) / 128), 256, GEMM_SMEM>>>(
        ath, wph, wpl, out, bproj, nullptr, MTOT, C_);
}

// round 17
// speedup vs baseline: 2.0289x; 1.3627x over previous
#include <cuda_runtime.h>
#include <cuda_fp16.h>
#include <cstdint>

#define H_    56
#define W_    56
#define NH_   12
#define HD    64
#define NTOK  3137          // 56*56 + 1
#define C_    768
#define C3    2304
#define B_    8
#define MTOT  (B_ * NTOK)   // 25096
#define KDIM  768
#define BK    64
#define NSTG  (KDIM / BK)   // 12
#define NCH   8
#define KC    393           // ceil(NTOK / NCH)

// ---------------- scratch (__device__ globals; no cudaMalloc allowed) -------
__device__ __half g_qkv[(size_t)MTOT * C3];   // fp16 QKV activations
__device__ __half g_att[(size_t)MTOT * C_];   // fp16 row-partial
__device__ __half g_sc [(size_t)B_ * NH_ * H_ * W_ * 64]; // col scores/probs fp16
__device__ float  g_clsp[(size_t)B_ * NH_ * NCH * 66];    // cls partials
__device__ __half g_xh [(size_t)MTOT * C_];   // x in fp16
__device__ __half g_ath[(size_t)MTOT * C_];   // attention out fp16
__device__ __half g_wq [(size_t)C3 * C_];     // W_qkv^T fp16 [N,K]
__device__ __half g_wp [(size_t)C_ * C_];     // W_proj^T fp16 [N,K]

__device__ __forceinline__ uint32_t hpack2(__half a, __half b) {
    return (uint32_t)__half_as_ushort(a) |
           ((uint32_t)__half_as_ushort(b) << 16);
}
__device__ __forceinline__ uint32_t su32(const void* p) {
    uint32_t a;
    asm("{ .reg .u64 t; cvta.to.shared.u64 t, %1; cvt.u32.u64 %0, t; }"
        : "=r"(a) : "l"(p));
    return a;
}
__device__ __forceinline__ void cp16(uint32_t dst, const void* src, bool ok) {
    int sz = ok ? 16 : 0;
    asm volatile("cp.async.cg.shared.global [%0], [%1], 16, %2;"
                 :: "r"(dst), "l"(src), "r"(sz) : "memory");
}
__device__ __forceinline__ void mma16816(float* c, const uint32_t* a, const uint32_t* b) {
    asm volatile(
        "mma.sync.aligned.m16n8k16.row.col.f32.f16.f16.f32 "
        "{%0,%1,%2,%3}, {%4,%5,%6,%7}, {%8,%9}, {%0,%1,%2,%3};"
        : "+f"(c[0]), "+f"(c[1]), "+f"(c[2]), "+f"(c[3])
        : "r"(a[0]), "r"(a[1]), "r"(a[2]), "r"(a[3]), "r"(b[0]), "r"(b[1]));
}
__device__ __forceinline__ void ldsm4(uint32_t& r0, uint32_t& r1, uint32_t& r2,
                                      uint32_t& r3, uint32_t addr) {
    asm volatile("ldmatrix.sync.aligned.m8n8.x4.shared.b16 {%0,%1,%2,%3}, [%4];"
                 : "=r"(r0), "=r"(r1), "=r"(r2), "=r"(r3) : "r"(addr));
}
__device__ __forceinline__ void ldsm4t(uint32_t& r0, uint32_t& r1, uint32_t& r2,
                                       uint32_t& r3, uint32_t addr) {
    asm volatile("ldmatrix.sync.aligned.m8n8.x4.trans.shared.b16 {%0,%1,%2,%3}, [%4];"
                 : "=r"(r0), "=r"(r1), "=r"(r2), "=r"(r3) : "r"(addr));
}

// ---------------- pre-pass: fp32 -> fp16 ------------------------------------
__global__ __launch_bounds__(256) void k_split(
    const float* __restrict__ in, __half* __restrict__ hi, int n4)
{
    int i = blockIdx.x * 256 + threadIdx.x;
    if (i >= n4) return;
    float4 v = ((const float4*)in)[i];
    __half hv[4];
    hv[0] = __float2half(v.x);
    hv[1] = __float2half(v.y);
    hv[2] = __float2half(v.z);
    hv[3] = __float2half(v.w);
    ((uint2*)hi)[i] = *(uint2*)hv;
}

// ---------------- pre-pass: transpose + fp16 weights [R,Cn] -> [Cn,R] -------
__global__ __launch_bounds__(256) void k_tsplit(
    const float* __restrict__ W, __half* __restrict__ th, int R, int Cn)
{
    __shared__ float t[32][33];
    int x = blockIdx.x * 32 + threadIdx.x;
    int y = blockIdx.y * 32 + threadIdx.y;
#pragma unroll
    for (int j = 0; j < 32; j += 8)
        t[threadIdx.y + j][threadIdx.x] = W[(size_t)(y + j) * Cn + x];
    __syncthreads();
    int ox = blockIdx.y * 32 + threadIdx.x;
    int oy = blockIdx.x * 32 + threadIdx.y;
#pragma unroll
    for (int j = 0; j < 32; j += 8)
        th[(size_t)(oy + j) * R + ox] = __float2half(t[threadIdx.x][threadIdx.y + j]);
}

// ---------------- fp16 GEMM: C = A[M,K] @ B[N,K]^T ---------------------------
// BK=64, 3-stage pipeline; fp32 out (+bias) when Oh==null, else fp16 staged out.
#define TS3     16384                 // one 128x64 fp16 tile
#define STG3    (2 * TS3)             // 32 KB per stage (A + B)
#define GEMM_SMEM (3 * STG3)          // 96 KB
#define CST     136                   // C-tile smem row stride in halves

__global__ __launch_bounds__(256) void gemm_mma(
    const __half* __restrict__ Ah, const __half* __restrict__ Bh,
    float* __restrict__ Cc, const float* __restrict__ bias,
    __half* __restrict__ Oh, int M, int N)
{
    extern __shared__ __align__(128) char smem[];
    const uint32_t sb = su32(smem);
    const int tid  = threadIdx.x;
    const int wid  = tid >> 5, lane = tid & 31;
    const int gid  = lane >> 2, tig = lane & 3;
    const int wm   = wid & 1, wn = wid >> 1;          // 2 x 4 warp grid
    const int row0 = blockIdx.y * 128, col0 = blockIdx.x * 128;

    float acc[4][4][4];
#pragma unroll
    for (int i = 0; i < 4; ++i)
#pragma unroll
        for (int j = 0; j < 4; ++j)
#pragma unroll
            for (int k = 0; k < 4; ++k) acc[i][j][k] = 0.f;

    // ldmatrix lane decomposition (full-XOR swizzle, row&7 == lane&7)
    const int swz = lane & 7;
    const int rA  = (lane & 7) + ((lane >> 3) & 1) * 8;   // A row in m16 tile
    const int cA  = (lane >> 4) & 1;                       // A k-chunk bit
    const int rB  = (lane & 7) + ((lane >> 4) & 1) * 8;   // B row in two n8 tiles
    const int cB  = (lane >> 3) & 1;                       // B k-chunk bit
    const uint32_t aRowOff = (uint32_t)(wm * 64 + rA) * 128u;
    const uint32_t bRowOff = (uint32_t)(wn * 32 + rB) * 128u + TS3;

    auto issue = [&](int c) {
        const int k0 = c * BK;
        const uint32_t stg = sb + (uint32_t)(c % 3) * STG3;
#pragma unroll
        for (int rep = 0; rep < 4; ++rep) {
            const int idx = tid + rep * 256;
            const int row = idx >> 3, cc = idx & 7;
            const uint32_t d = stg + (uint32_t)row * 128u
                             + (uint32_t)((cc ^ (row & 7)) * 16);
            const int grA = row0 + row;
            const bool okA = grA < M;
            cp16(d, Ah + (size_t)(okA ? grA : 0) * KDIM + k0 + cc * 8, okA);
            cp16(d + TS3, Bh + (size_t)(col0 + row) * KDIM + k0 + cc * 8, true);
        }
        asm volatile("cp.async.commit_group;" ::: "memory");
    };

    issue(0);
    issue(1);

    for (int c = 0; c < NSTG; ++c) {
        if (c + 1 < NSTG)
            asm volatile("cp.async.wait_group 1;" ::: "memory");
        else
            asm volatile("cp.async.wait_group 0;" ::: "memory");
        __syncthreads();
        if (c + 2 < NSTG) issue(c + 2);

        const uint32_t stg = sb + (uint32_t)(c % 3) * STG3;

#pragma unroll
        for (int kk = 0; kk < 4; ++kk) {
            const uint32_t aCh = (uint32_t)(((2 * kk + cA) ^ swz) * 16);
            const uint32_t bCh = (uint32_t)(((2 * kk + cB) ^ swz) * 16);
            uint32_t a[4][4], bb[4][2];
#pragma unroll
            for (int mt = 0; mt < 4; ++mt)
                ldsm4(a[mt][0], a[mt][1], a[mt][2], a[mt][3],
                      stg + aRowOff + mt * (16 * 128) + aCh);
#pragma unroll
            for (int pr = 0; pr < 2; ++pr)
                ldsm4(bb[2 * pr][0], bb[2 * pr][1], bb[2 * pr + 1][0], bb[2 * pr + 1][1],
                      stg + bRowOff + pr * (16 * 128) + bCh);
#pragma unroll
            for (int mt = 0; mt < 4; ++mt)
#pragma unroll
                for (int nt = 0; nt < 4; ++nt) mma16816(acc[mt][nt], a[mt], bb[nt]);
        }
    }

    if (Oh != nullptr) {
        __syncthreads();
        __half* ct = (__half*)smem;
#pragma unroll
        for (int mt = 0; mt < 4; ++mt) {
            const int lr = wm * 64 + mt * 16 + gid;
#pragma unroll
            for (int nt = 0; nt < 4; ++nt) {
                const int lc = wn * 32 + nt * 8 + tig * 2;
                *(uint32_t*)&ct[lr * CST + lc] =
                    hpack2(__float2half(acc[mt][nt][0]), __float2half(acc[mt][nt][1]));
                *(uint32_t*)&ct[(lr + 8) * CST + lc] =
                    hpack2(__float2half(acc[mt][nt][2]), __float2half(acc[mt][nt][3]));
            }
        }
        __syncthreads();
        for (int idx = tid; idx < 2048; idx += 256) {
            const int r = idx >> 4, ch = idx & 15;
            const int gr = row0 + r;
            if (gr < M)
                *(uint4*)(Oh + (size_t)gr * N + col0 + ch * 8) =
                    *(const uint4*)&ct[r * CST + ch * 8];
        }
    } else {
#pragma unroll
        for (int mt = 0; mt < 4; ++mt) {
            const int gr = row0 + wm * 64 + mt * 16 + gid;
#pragma unroll
            for (int nt = 0; nt < 4; ++nt) {
                const int gc = col0 + wn * 32 + nt * 8 + tig * 2;
                float b0 = 0.f, b1 = 0.f;
                if (bias) { b0 = __ldg(bias + gc); b1 = __ldg(bias + gc + 1); }
                if (gr < M)
                    *(float2*)(Cc + (size_t)gr * N + gc) =
                        make_float2(acc[mt][nt][0] + b0, acc[mt][nt][1] + b1);
                if (gr + 8 < M)
                    *(float2*)(Cc + (size_t)(gr + 8) * N + gc) =
                        make_float2(acc[mt][nt][2] + b0, acc[mt][nt][3] + b1);
            }
        }
    }
}

// ============================================================================
// Attention MMA helpers: 64x64 fp16 tiles, 128B rows, chunk swizzle c^(row&7)
// ============================================================================
#define ATS 8192   // one 64x64 fp16 tile

template <bool TRANS>
__device__ __forceinline__ void att_mma64(
    float (&acc)[8][4], uint32_t sA, uint32_t sB, int m0, int lane)
{
    const int rA = (lane & 7) + ((lane >> 3) & 1) * 8;
    const int cA = (lane >> 4) & 1;
#pragma unroll
    for (int s = 0; s < 4; ++s) {
        uint32_t a[4];
        {
            const int row = m0 + rA;
            const uint32_t ad = sA + (uint32_t)row * 128u
                              + (uint32_t)(((2 * s + cA) ^ (row & 7)) * 16);
            ldsm4(a[0], a[1], a[2], a[3], ad);
        }
        uint32_t bb[8][2];
#pragma unroll
        for (int p = 0; p < 4; ++p) {
            uint32_t ad;
            if (TRANS) {
                const int row = s * 16 + (lane & 7) + ((lane >> 3) & 1) * 8;
                const int ch  = 2 * p + ((lane >> 4) & 1);
                ad = sB + (uint32_t)row * 128u + (uint32_t)((ch ^ (row & 7)) * 16);
                ldsm4t(bb[2 * p][0], bb[2 * p][1], bb[2 * p + 1][0], bb[2 * p + 1][1], ad);
            } else {
                const int row = p * 16 + (lane & 7) + ((lane >> 4) & 1) * 8;
                const int ch  = 2 * s + ((lane >> 3) & 1);
                ad = sB + (uint32_t)row * 128u + (uint32_t)((ch ^ (row & 7)) * 16);
                ldsm4(bb[2 * p][0], bb[2 * p][1], bb[2 * p + 1][0], bb[2 * p + 1][1], ad);
            }
        }
#pragma unroll
        for (int nt = 0; nt < 8; ++nt) mma16816(acc[nt], a, bb[nt]);
    }
}

#define TILE_LOAD1(T, NMAP, RMAX, GOFF)                                        \
    for (int idx = tid; idx < 512; idx += 128) {                               \
        const int r = idx >> 3, cc = idx & 7;                                  \
        const uint32_t d = (uint32_t)r * 128u + (uint32_t)((cc ^ (r & 7)) * 16); \
        uint4 v = make_uint4(0, 0, 0, 0);                                      \
        if (r < (RMAX)) {                                                      \
            const int n = (NMAP);                                              \
            v = *(const uint4*)(qk + (size_t)n * C3 + (GOFF) + cc * 8);        \
        }                                                                      \
        *(uint4*)((T) + d) = v;                                                \
    }

// ============================================================================
// Phase 1: column scores via fp16 MMA. Block=(w, head, b), 128 threads.
// ============================================================================
__global__ __launch_bounds__(128) void k_colscore(
    const __half* __restrict__ qkv, __half* __restrict__ sc)
{
    __shared__ __align__(16) char sm[2 * ATS];
    char* T0 = sm;              // Q
    char* T2 = sm + ATS;        // K
    const int w = blockIdx.x, head = blockIdx.y, b = blockIdx.z;
    const int tid = threadIdx.x, wid = tid >> 5, lane = tid & 31;
    const __half* qk = qkv + (size_t)b * NTOK * C3;
    const int qoff = head * HD;

    TILE_LOAD1(T0, 1 + r * W_ + w, 56, qoff)
    TILE_LOAD1(T2, (r == 0) ? 0 : (1 + (r - 1) * W_ + w), 57, C_ + qoff)
    __syncthreads();

    float acc[8][4];
#pragma unroll
    for (int i = 0; i < 8; ++i)
#pragma unroll
        for (int j = 0; j < 4; ++j) acc[i][j] = 0.f;

    att_mma64<false>(acc, su32(T0), su32(T2), wid * 16, lane);

    __half* out = sc + ((((size_t)b * NH_ + head) * H_) * W_ + w) * 64;
    const int crow = wid * 16 + (lane >> 2);
    const int ccol = (lane & 3) * 2;
#pragma unroll
    for (int nt = 0; nt < 8; ++nt)
#pragma unroll
        for (int i = 0; i < 4; ++i) {
            const int row = crow + (i >> 1) * 8;
            const int col = nt * 8 + ccol + (i & 1);
            if (row < 56 && col < 57)
                out[(size_t)row * (W_ * 64) + col] = __float2half(acc[nt][i] * 0.125f);
        }
}

// ============================================================================
// Phase 2: row scores (MMA) + full softmax + row P·V (MMA).
// ============================================================================
#define PST 132
#define RF_SMEM (2 * ATS + 64 * PST * 4)   // 16384 + 33792 = 50176

__global__ __launch_bounds__(128) void k_rowfused(
    const __half* __restrict__ qkv, __half* __restrict__ sc,
    __half* __restrict__ attp)
{
    extern __shared__ __align__(16) char dsm[];
    char* T0 = dsm;              // Q -> P(fp16)
    char* T2 = dsm + ATS;        // K -> V
    float* P = (float*)(dsm + 2 * ATS);

    const int h = blockIdx.x, head = blockIdx.y, b = blockIdx.z;
    const int tid = threadIdx.x, wid = tid >> 5, lane = tid & 31;
    const __half* qk = qkv + (size_t)b * NTOK * C3;
    const int qoff = head * HD;
    const int nrow0 = 1 + h * W_;

    TILE_LOAD1(T0, nrow0 + r, 56, qoff)
    TILE_LOAD1(T2, nrow0 + r, 56, C_ + qoff)
    __syncthreads();

    {
        float acc[8][4];
#pragma unroll
        for (int i = 0; i < 8; ++i)
#pragma unroll
            for (int j = 0; j < 4; ++j) acc[i][j] = 0.f;
        att_mma64<false>(acc, su32(T0), su32(T2), wid * 16, lane);

        const int crow = wid * 16 + (lane >> 2);
        const int ccol = (lane & 3) * 2;
#pragma unroll
        for (int nt = 0; nt < 8; ++nt)
#pragma unroll
            for (int i = 0; i < 4; ++i) {
                const int row = crow + (i >> 1) * 8;
                const int col = nt * 8 + ccol + (i & 1);
                float v = acc[nt][i] * 0.125f;
                if (col == row || col >= 56) v = -1e30f;
                P[row * PST + 60 + col] = v;
            }
    }
    __syncthreads();

    {
        const __half* scb = sc + ((((size_t)b * NH_ + head) * H_ + h) * W_) * 64;
        for (int idx = tid; idx < 56 * 57; idx += 128) {
            const int q = idx / 57, j = idx % 57;
            P[q * PST + j] = __half2float(scb[(size_t)q * 64 + j]);
        }
    }
    TILE_LOAD1(T2, nrow0 + r, 56, 2 * C_ + qoff)
    __syncthreads();

    if (tid < 56) {
        float* row = P + tid * PST;
        float m = -1e30f;
#pragma unroll 4
        for (int j = 0; j < 57; ++j) m = fmaxf(m, row[j]);
#pragma unroll 4
        for (int j = 60; j < 116; ++j) m = fmaxf(m, row[j]);
        float s = 0.f;
#pragma unroll 4
        for (int j = 0; j < 57; ++j) { float e = __expf(row[j] - m); row[j] = e; s += e; }
#pragma unroll 4
        for (int j = 60; j < 116; ++j) { float e = __expf(row[j] - m); row[j] = e; s += e; }
        const float inv = 1.f / s;
#pragma unroll 4
        for (int j = 0; j < 57; ++j) row[j] *= inv;
#pragma unroll 4
        for (int j = 60; j < 116; ++j) row[j] *= inv;
    }
    __syncthreads();

    {
        __half* scb = sc + ((((size_t)b * NH_ + head) * H_ + h) * W_) * 64;
        for (int idx = tid; idx < 56 * 57; idx += 128) {
            const int q = idx / 57, j = idx % 57;
            scb[(size_t)q * 64 + j] = __float2half(P[q * PST + j]);
        }
        for (int idx = tid; idx < 4096; idx += 128) {
            const int q = idx >> 6, k = idx & 63;
            float v = (q < 56 && k < 56) ? P[q * PST + 60 + k] : 0.f;
            const uint32_t d = (uint32_t)q * 128u
                             + (uint32_t)((((k >> 3) ^ (q & 7)) * 16) + (k & 7) * 2);
            *(__half*)(T0 + d) = __float2half(v);
        }
    }
    __syncthreads();

    {
        float acc[8][4];
#pragma unroll
        for (int i = 0; i < 8; ++i)
#pragma unroll
            for (int j = 0; j < 4; ++j) acc[i][j] = 0.f;
        att_mma64<true>(acc, su32(T0), su32(T2), wid * 16, lane);

        const int crow = wid * 16 + (lane >> 2);
        const int ccol = (lane & 3) * 2;
#pragma unroll
        for (int nt = 0; nt < 8; ++nt) {
            const int col = nt * 8 + ccol;
            const int r0 = crow, r1 = crow + 8;
            if (r0 < 56)
                *(uint32_t*)(attp + ((size_t)b * NTOK + nrow0 + r0) * C_ + qoff + col)
                    = hpack2(__float2half(acc[nt][0]), __float2half(acc[nt][1]));
            if (r1 < 56)
                *(uint32_t*)(attp + ((size_t)b * NTOK + nrow0 + r1) * C_ + qoff + col)
                    = hpack2(__float2half(acc[nt][2]), __float2half(acc[nt][3]));
        }
    }
}

// ============================================================================
// Phase 3: column aggregation (MMA) + fp16 emit. Block=(w, head, b).
// ============================================================================
__global__ __launch_bounds__(128) void k_colagg(
    const __half* __restrict__ qkv, const __half* __restrict__ sc,
    const __half* __restrict__ attp, __half* __restrict__ outh)
{
    __shared__ __align__(16) char sm[2 * ATS];
    char* T0 = sm;              // P col (fp16)
    char* T2 = sm + ATS;        // V col
    const int w = blockIdx.x, head = blockIdx.y, b = blockIdx.z;
    const int tid = threadIdx.x, wid = tid >> 5, lane = tid & 31;
    const __half* qk = qkv + (size_t)b * NTOK * C3;
    const int qoff = head * HD;

    TILE_LOAD1(T2, (r == 0) ? 0 : (1 + (r - 1) * W_ + w), 57, 2 * C_ + qoff)
    {
        const __half* scb = sc + (((size_t)b * NH_ + head) * H_) * (W_ * 64)
                          + (size_t)w * 64;
        for (int idx = tid; idx < 4096; idx += 128) {
            const int q = idx >> 6, k = idx & 63;
            __half v = (q < 56 && k < 57) ? scb[(size_t)q * (W_ * 64) + k]
                                          : __float2half(0.f);
            const uint32_t d = (uint32_t)q * 128u
                             + (uint32_t)((((k >> 3) ^ (q & 7)) * 16) + (k & 7) * 2);
            *(__half*)(T0 + d) = v;
        }
    }
    __syncthreads();

    float acc[8][4];
#pragma unroll
    for (int i = 0; i < 8; ++i)
#pragma unroll
        for (int j = 0; j < 4; ++j) acc[i][j] = 0.f;
    att_mma64<true>(acc, su32(T0), su32(T2), wid * 16, lane);

    const int crow = wid * 16 + (lane >> 2);
    const int ccol = (lane & 3) * 2;
#pragma unroll
    for (int nt = 0; nt < 8; ++nt) {
        const int col = nt * 8 + ccol;
#pragma unroll
        for (int half = 0; half < 2; ++half) {
            const int row = crow + half * 8;
            if (row >= 56) continue;
            const size_t off = ((size_t)b * NTOK + 1 + row * W_ + w) * C_ + qoff + col;
            const float2 rp = __half22float2(*(const __half2*)(attp + off));
            *(uint32_t*)(outh + off) =
                hpack2(__float2half(acc[nt][2 * half + 0] + rp.x),
                       __float2half(acc[nt][2 * half + 1] + rp.y));
        }
    }
}

// ---------------- CLS-token attention: split-K partials + reduce ------------
__global__ __launch_bounds__(256) void cls_part(
    const __half* __restrict__ qkv, float* __restrict__ clsp)
{
    const int nh = blockIdx.x, b = blockIdx.y, ch = blockIdx.z;
    const int tid = threadIdx.x;
    const int n0 = ch * KC;
    const int n1 = min(NTOK, n0 + KC);
    const int cnt = n1 - n0;

    __shared__ float qs[HD];
    __shared__ float scs[KC];
    __shared__ float red[256];
    __shared__ float part[4][HD];

    const __half* base = qkv + (size_t)b * NTOK * C3;
    if (tid < HD) qs[tid] = __half2float(base[nh * HD + tid]);
    __syncthreads();

    for (int i = tid; i < cnt; i += 256) {
        const __half2* kp = (const __half2*)(base + (size_t)(n0 + i) * C3 + C_ + nh * HD);
        float s = 0.f;
#pragma unroll
        for (int d = 0; d < HD / 2; ++d) {
            float2 kv = __half22float2(kp[d]);
            s += qs[2 * d] * kv.x + qs[2 * d + 1] * kv.y;
        }
        scs[i] = s * 0.125f;
    }
    __syncthreads();

    float m = -1e30f;
    for (int i = tid; i < cnt; i += 256) m = fmaxf(m, scs[i]);
    red[tid] = m;
    __syncthreads();
    for (int st = 128; st; st >>= 1) {
        if (tid < st) red[tid] = fmaxf(red[tid], red[tid + st]);
        __syncthreads();
    }
    m = red[0];
    __syncthreads();

    float s = 0.f;
    for (int i = tid; i < cnt; i += 256) {
        float e = __expf(scs[i] - m);
        scs[i] = e;
        s += e;
    }
    red[tid] = s;
    __syncthreads();
    for (int st = 128; st; st >>= 1) {
        if (tid < st) red[tid] += red[tid + st];
        __syncthreads();
    }
    const float S = red[0];
    __syncthreads();

    const int d = tid & 63, kq = tid >> 6;
    float acc = 0.f;
    for (int i = kq; i < cnt; i += 4)
        acc += scs[i] * __half2float(base[(size_t)(n0 + i) * C3 + 2 * C_ + nh * HD + d]);
    part[kq][d] = acc;
    __syncthreads();
    if (kq == 0) {
        float* o = clsp + ((size_t)(b * NH_ + nh) * NCH + ch) * 66;
        o[d] = part[0][d] + part[1][d] + part[2][d] + part[3][d];
        if (d == 0) { o[64] = m; o[65] = S; }
    }
}

__global__ __launch_bounds__(64) void cls_reduce(
    const float* __restrict__ clsp, __half* __restrict__ outh)
{
    const int nh = blockIdx.x, b = blockIdx.y;
    const int d = threadIdx.x;
    const float* o = clsp + (size_t)(b * NH_ + nh) * NCH * 66;
    float M = -1e30f;
#pragma unroll
    for (int c = 0; c < NCH; ++c) M = fmaxf(M, o[c * 66 + 64]);
    float S = 0.f, A = 0.f;
#pragma unroll
    for (int c = 0; c < NCH; ++c) {
        const float wgt = __expf(o[c * 66 + 64] - M);
        S += o[c * 66 + 65] * wgt;
        A += o[c * 66 + d] * wgt;
    }
    outh[(size_t)b * NTOK * C_ + nh * HD + d] = __float2half(A / S);
}

// ---------------------------------------------------------------------------
extern "C" void kernel_launch(void* const* d_in, const int* in_sizes, int n_in,
                              void* d_out, int out_size)
{
    const float* x     = (const float*)d_in[0];
    const float* Wqkv  = (const float*)d_in[1];
    const float* Wproj = (const float*)d_in[2];
    const float* bproj = (const float*)d_in[3];
    float* out = (float*)d_out;

    float *clsp;
    __half *qkv, *att, *sc, *xh, *ath, *wq, *wp;
    cudaGetSymbolAddress((void**)&qkv,  g_qkv);
    cudaGetSymbolAddress((void**)&att,  g_att);
    cudaGetSymbolAddress((void**)&sc,   g_sc);
    cudaGetSymbolAddress((void**)&clsp, g_clsp);
    cudaGetSymbolAddress((void**)&xh,   g_xh);
    cudaGetSymbolAddress((void**)&ath,  g_ath);
    cudaGetSymbolAddress((void**)&wq,   g_wq);
    cudaGetSymbolAddress((void**)&wp,   g_wp);

    cudaFuncSetAttribute(gemm_mma,
                         cudaFuncAttributeMaxDynamicSharedMemorySize, GEMM_SMEM);
    cudaFuncSetAttribute(k_rowfused,
                         cudaFuncAttributeMaxDynamicSharedMemorySize, RF_SMEM);

    // 0) pre-passes
    {
        int n4 = MTOT * C_ / 4;
        k_split<<<(n4 + 255) / 256, 256>>>(x, xh, n4);
        k_tsplit<<<dim3(C3 / 32, C_ / 32), dim3(32, 8)>>>(Wqkv,  wq, C_, C3);
        k_tsplit<<<dim3(C_ / 32, C_ / 32), dim3(32, 8)>>>(Wproj, wp, C_, C_);
    }
    // 1) QKV projection -> fp16 qkv (single-pass fp16, BK=64, 3-stage)
    gemm_mma<<<dim3(C3 / 128, (MTOT + 127) / 128), 256, GEMM_SMEM>>>(
        xh, wq, nullptr, nullptr, qkv, MTOT, C3);
    // 2) attention phases (fp16 MMA, fp16 scratch)
    {
        dim3 ag(W_, NH_, B_);
        k_colscore<<<ag, 128>>>(qkv, sc);
        dim3 rg(H_, NH_, B_);
        k_rowfused<<<rg, 128, RF_SMEM>>>(qkv, sc, att);
        cls_part<<<dim3(NH_, B_, NCH), 256>>>(qkv, clsp);
        cls_reduce<<<dim3(NH_, B_), 64>>>(clsp, ath);
        k_colagg<<<ag, 128>>>(qkv, sc, att, ath);
    }
    // 3) output projection + bias (fp32 out)
    gemm_mma<<<dim3(C_ / 128, (MTOT + 127) / 128), 256, GEMM_SMEM>>>(
        ath, wp, out, bproj, nullptr, MTOT, C_);
}